// round 2
// baseline (speedup 1.0000x reference)
#include <cuda_runtime.h>
#include <cstdint>
#include <math.h>

#define N_TOK 1024
#define HID   2048
#define NEXP  8
#define IMOE  1408
#define ISH   5632

// ---------------- scratch (device globals; no allocation allowed) ----------------
__device__ float g_gu_s [(size_t)N_TOK * (2 * ISH)];        // shared gate_up out
__device__ float g_act_s[(size_t)N_TOK * ISH];              // shared activated
__device__ float g_gu_e [(size_t)NEXP * N_TOK * (2 * IMOE)];// expert gate_up out (compact)
__device__ float g_act_e[(size_t)NEXP * N_TOK * IMOE];      // expert activated (weighted)
__device__ float g_sg  [N_TOK];                             // sigmoid shared gate
__device__ float g_wt  [NEXP * N_TOK];                      // routing weight per list entry
__device__ int   g_cnt [NEXP];
__device__ int   g_tok [NEXP * N_TOK];

// ---------------- small helpers ----------------
__device__ __forceinline__ float siluf(float v) { return v / (1.f + expf(-v)); }

__device__ __forceinline__ unsigned f2tf(float f) {
    unsigned r; asm("cvt.rna.tf32.f32 %0, %1;" : "=r"(r) : "f"(f)); return r;
}
__device__ __forceinline__ void mma_tf32(float* c, const unsigned* a, const unsigned* b) {
    asm volatile(
        "mma.sync.aligned.m16n8k8.row.col.f32.tf32.tf32.f32 "
        "{%0,%1,%2,%3}, {%4,%5,%6,%7}, {%8,%9}, {%0,%1,%2,%3};\n"
        : "+f"(c[0]), "+f"(c[1]), "+f"(c[2]), "+f"(c[3])
        : "r"(a[0]), "r"(a[1]), "r"(a[2]), "r"(a[3]), "r"(b[0]), "r"(b[1]));
}
__device__ __forceinline__ void cp16(uint32_t dst, const float* src) {
    asm volatile("cp.async.cg.shared.global [%0], [%1], 16;\n" :: "r"(dst), "l"(src));
}
__device__ __forceinline__ void cp_commit() { asm volatile("cp.async.commit_group;\n"); }
template<int W> __device__ __forceinline__ void cp_wait() {
    asm volatile("cp.async.wait_group %0;\n" :: "n"(W));
}

// ---------------- init: zero per-expert counters (must run every replay) ----------------
__global__ void init_kernel() {
    if (threadIdx.x < NEXP) g_cnt[threadIdx.x] = 0;
}

// ---------------- router: logits, softmax, top-2, sigmoid shared gate ----------------
__global__ void router_kernel(const float* __restrict__ x,
                              const float* __restrict__ gate_w,
                              const float* __restrict__ sgate_w) {
    int n = blockIdx.x;
    int w = threadIdx.x >> 5, lane = threadIdx.x & 31;
    const float* xr = x + (size_t)n * HID;
    __shared__ float s_log[NEXP];
    __shared__ float s_sg;

    float acc = 0.f, accs = 0.f;
    for (int h = lane; h < HID; h += 32) {
        float xv = xr[h];
        acc += xv * gate_w[h * NEXP + w];
        if (w == 0) accs += xv * sgate_w[h];
    }
    #pragma unroll
    for (int o = 16; o > 0; o >>= 1) {
        acc  += __shfl_down_sync(0xffffffffu, acc, o);
        accs += __shfl_down_sync(0xffffffffu, accs, o);
    }
    if (lane == 0) { s_log[w] = acc; if (w == 0) s_sg = accs; }
    __syncthreads();

    if (threadIdx.x == 0) {
        float mx = s_log[0];
        #pragma unroll
        for (int e = 1; e < NEXP; e++) mx = fmaxf(mx, s_log[e]);
        float p[NEXP], den = 0.f;
        #pragma unroll
        for (int e = 0; e < NEXP; e++) { p[e] = expf(s_log[e] - mx); den += p[e]; }
        float inv = 1.f / den;
        #pragma unroll
        for (int e = 0; e < NEXP; e++) p[e] *= inv;
        int e0 = 0;
        #pragma unroll
        for (int e = 1; e < NEXP; e++) if (p[e] > p[e0]) e0 = e;
        int e1 = (e0 == 0) ? 1 : 0;
        #pragma unroll
        for (int e = 0; e < NEXP; e++) if (e != e0 && p[e] > p[e1]) e1 = e;
        int es[2] = {e0, e1};
        #pragma unroll
        for (int k = 0; k < 2; k++) {
            int e = es[k];
            int pos = atomicAdd(&g_cnt[e], 1);
            g_tok[e * N_TOK + pos] = n;
            g_wt [e * N_TOK + pos] = p[e];
        }
        g_sg[n] = 1.f / (1.f + expf(-s_sg));
    }
}

// ---------------- tf32 GEMM, 128x256x16 tile, 256 threads, 4-stage cp.async ----------------
// MODE 0: g_gu_s = x @ shared_w_gate_up                     [1024,2048]x[2048,11264]
// MODE 1: out    = act_s @ shared_w_down * sg[row]          [1024,5632]x[5632,2048]
// MODE 2: g_gu_e[e] = gather(x) @ w_gate_up[e]              [cnt,2048]x[2048,2816]
// MODE 3: out   += g_act_e[e] @ w_down[e]   (atomic scatter)[cnt,1408]x[1408,2048]
#define BM 128
#define BN 256
#define BK 16
#define GT 256
#define STAGES 4
#define A_LD (BK + 4)
#define B_LD (BN + 8)
#define A_TILE (BM * A_LD)
#define B_TILE (BK * B_LD)
#define SMEM_FLOATS (STAGES * (A_TILE + B_TILE))

template<int MODE>
__global__ void __launch_bounds__(GT, 1)
gemm_tf32(const float* __restrict__ Ag, const float* __restrict__ Bg,
          float* __restrict__ Cg, int M, int K, int N) {
    extern __shared__ float smem[];
    float* As = smem;                         // [STAGES][BM][A_LD]
    float* Bs = smem + STAGES * A_TILE;       // [STAGES][BK][B_LD]

    const int tid  = threadIdx.x;
    const int lane = tid & 31, warp = tid >> 5;
    const int wm = warp & 1, wn = warp >> 1;     // 2x4 warp grid, 64x64 warp tile
    const int g = lane >> 2, tg = lane & 3;

    const int m0 = blockIdx.y * BM;
    const int n0 = blockIdx.x * BN;
    const int e  = blockIdx.z;

    int Mrows = M;
    const float* B = Bg;
    if (MODE == 2 || MODE == 3) {
        Mrows = g_cnt[e];
        B = Bg + (size_t)e * (size_t)K * (size_t)N;
        if (m0 >= Mrows) return;
    }

    const float* Abase;
    if (MODE == 1)      Abase = g_act_s;
    else if (MODE == 3) Abase = g_act_e + (size_t)e * N_TOK * (size_t)K;
    else                Abase = Ag;

    // A loader: 2 rows x 16B per thread per stage
    const int lr0 = tid >> 2;            // 0..63
    const int ka  = (tid & 3) * 4;
    const float *aP0, *aP1;
    {
        int rr0 = m0 + lr0, rr1 = m0 + lr0 + 64;
        if (MODE == 2) {
            int i0 = (rr0 < Mrows) ? g_tok[e * N_TOK + rr0] : 0;
            int i1 = (rr1 < Mrows) ? g_tok[e * N_TOK + rr1] : 0;
            aP0 = Ag + (size_t)i0 * (size_t)K;
            aP1 = Ag + (size_t)i1 * (size_t)K;
        } else {
            aP0 = Abase + (size_t)rr0 * (size_t)K;
            aP1 = Abase + (size_t)rr1 * (size_t)K;
        }
    }
    // B loader: 4 rows x 16B per thread per stage
    const int br = tid >> 6;             // 0..3 (+4r)
    const int bc = (tid & 63) * 4;       // 0..252

    uint32_t sA = (uint32_t)__cvta_generic_to_shared(As);
    uint32_t sB = (uint32_t)__cvta_generic_to_shared(Bs);
    const uint32_t dA0 = sA + (uint32_t)(lr0 * A_LD + ka) * 4u;
    const uint32_t dA1 = dA0 + (uint32_t)(64 * A_LD) * 4u;
    const uint32_t dB0 = sB + (uint32_t)(br * B_LD + bc) * 4u;

    const int ktiles = K / BK;

    float acc[4][8][4];
    #pragma unroll
    for (int i = 0; i < 4; i++)
        #pragma unroll
        for (int j = 0; j < 8; j++)
            #pragma unroll
            for (int q = 0; q < 4; q++) acc[i][j][q] = 0.f;

    // prologue: issue STAGES-1 stages
    #pragma unroll
    for (int s = 0; s < STAGES - 1; s++) {
        const int k0 = s * BK;
        cp16(dA0 + (uint32_t)(s * A_TILE) * 4u, aP0 + k0 + ka);
        cp16(dA1 + (uint32_t)(s * A_TILE) * 4u, aP1 + k0 + ka);
        const float* bp = B + (size_t)(k0 + br) * N + n0 + bc;
        #pragma unroll
        for (int r = 0; r < 4; r++)
            cp16(dB0 + (uint32_t)(s * B_TILE + r * 4 * B_LD) * 4u, bp + (size_t)(r * 4) * N);
        cp_commit();
    }

    for (int kt = 0; kt < ktiles; kt++) {
        cp_wait<STAGES - 2>();
        __syncthreads();

        const int kn = kt + STAGES - 1;
        if (kn < ktiles) {
            const int st = kn & (STAGES - 1);
            const int k0 = kn * BK;
            cp16(dA0 + (uint32_t)(st * A_TILE) * 4u, aP0 + k0 + ka);
            cp16(dA1 + (uint32_t)(st * A_TILE) * 4u, aP1 + k0 + ka);
            const float* bp = B + (size_t)(k0 + br) * N + n0 + bc;
            #pragma unroll
            for (int r = 0; r < 4; r++)
                cp16(dB0 + (uint32_t)(st * B_TILE + r * 4 * B_LD) * 4u, bp + (size_t)(r * 4) * N);
        }
        cp_commit();

        const float* a_ = As + (kt & (STAGES - 1)) * A_TILE;
        const float* b_ = Bs + (kt & (STAGES - 1)) * B_TILE;
        #pragma unroll
        for (int ks = 0; ks < 2; ks++) {
            const int kk = ks * 8;
            unsigned af[4][4], bf[8][2];
            #pragma unroll
            for (int i = 0; i < 4; i++) {
                const float* ar = a_ + (wm * 64 + i * 16 + g) * A_LD + kk + tg;
                af[i][0] = f2tf(ar[0]);
                af[i][1] = f2tf(ar[8 * A_LD]);
                af[i][2] = f2tf(ar[4]);
                af[i][3] = f2tf(ar[8 * A_LD + 4]);
            }
            #pragma unroll
            for (int j = 0; j < 8; j++) {
                const float* brp = b_ + (kk + tg) * B_LD + wn * 64 + j * 8 + g;
                bf[j][0] = f2tf(brp[0]);
                bf[j][1] = f2tf(brp[4 * B_LD]);
            }
            #pragma unroll
            for (int i = 0; i < 4; i++)
                #pragma unroll
                for (int j = 0; j < 8; j++)
                    mma_tf32(acc[i][j], af[i], bf[j]);
        }
    }

    // epilogue
    #pragma unroll
    for (int i = 0; i < 4; i++) {
        #pragma unroll
        for (int half = 0; half < 2; half++) {
            int lr = wm * 64 + i * 16 + g + half * 8;
            int gr = m0 + lr;
            if ((MODE == 2 || MODE == 3) && gr >= Mrows) continue;
            if (MODE == 3) {
                int t_ = g_tok[e * N_TOK + gr];
                float* crow = Cg + (size_t)t_ * (size_t)N;
                #pragma unroll
                for (int j = 0; j < 8; j++) {
                    int cc = n0 + wn * 64 + j * 8 + 2 * tg;
                    atomicAdd(crow + cc,     acc[i][j][half * 2 + 0]);
                    atomicAdd(crow + cc + 1, acc[i][j][half * 2 + 1]);
                }
            } else {
                float scale = 1.f;
                float* crow;
                if (MODE == 0)      crow = g_gu_s + (size_t)gr * (size_t)N;
                else if (MODE == 1) { crow = Cg + (size_t)gr * (size_t)N; scale = g_sg[gr]; }
                else                crow = g_gu_e + ((size_t)e * N_TOK + gr) * (size_t)N;
                #pragma unroll
                for (int j = 0; j < 8; j++) {
                    int cc = n0 + wn * 64 + j * 8 + 2 * tg;
                    float2 v = make_float2(acc[i][j][half * 2 + 0] * scale,
                                           acc[i][j][half * 2 + 1] * scale);
                    *(float2*)(crow + cc) = v;
                }
            }
        }
    }
}

// ---------------- elementwise: shared silu*up ----------------
__global__ void silu_shared_kernel() {
    int idx = blockIdx.x * blockDim.x + threadIdx.x;
    const int total = N_TOK * (ISH / 4);
    if (idx >= total) return;
    int n  = idx / (ISH / 4);
    int i4 = (idx % (ISH / 4)) * 4;
    const float* row = g_gu_s + (size_t)n * (2 * ISH);
    float4 gv = *(const float4*)(row + i4);
    float4 uv = *(const float4*)(row + ISH + i4);
    float4 o = make_float4(siluf(gv.x) * uv.x, siluf(gv.y) * uv.y,
                           siluf(gv.z) * uv.z, siluf(gv.w) * uv.w);
    *(float4*)(g_act_s + (size_t)n * ISH + i4) = o;
}

// ---------------- elementwise: expert silu*up, scaled by routing weight ----------------
__global__ void silu_expert_kernel() {
    int idx = blockIdx.x * blockDim.x + threadIdx.x;
    const int per = IMOE / 4;                 // 352
    const int total = NEXP * N_TOK * per;
    if (idx >= total) return;
    int e   = idx / (N_TOK * per);
    int rem = idx % (N_TOK * per);
    int m   = rem / per;
    int i4  = (rem % per) * 4;
    if (m >= g_cnt[e]) return;
    float w = g_wt[e * N_TOK + m];
    const float* row = g_gu_e + ((size_t)e * N_TOK + m) * (2 * IMOE);
    float4 gv = *(const float4*)(row + i4);
    float4 uv = *(const float4*)(row + IMOE + i4);
    float4 o = make_float4(w * siluf(gv.x) * uv.x, w * siluf(gv.y) * uv.y,
                           w * siluf(gv.z) * uv.z, w * siluf(gv.w) * uv.w);
    *(float4*)(g_act_e + ((size_t)e * N_TOK + m) * IMOE + i4) = o;
}

// ---------------- launch ----------------
extern "C" void kernel_launch(void* const* d_in, const int* in_sizes, int n_in,
                              void* d_out, int out_size) {
    const float* x    = (const float*)d_in[0];   // [1024, 2048]
    const float* gw   = (const float*)d_in[1];   // [2048, 8]
    const float* wgu  = (const float*)d_in[2];   // [8, 2048, 2816]
    const float* wd   = (const float*)d_in[3];   // [8, 1408, 2048]
    const float* swgu = (const float*)d_in[4];   // [2048, 11264]
    const float* swd  = (const float*)d_in[5];   // [5632, 2048]
    const float* sgw  = (const float*)d_in[6];   // [2048, 1]
    float* out = (float*)d_out;                  // [1024, 2048]

    const int smem_bytes = SMEM_FLOATS * 4;      // 108544
    cudaFuncSetAttribute(gemm_tf32<0>, cudaFuncAttributeMaxDynamicSharedMemorySize, smem_bytes);
    cudaFuncSetAttribute(gemm_tf32<1>, cudaFuncAttributeMaxDynamicSharedMemorySize, smem_bytes);
    cudaFuncSetAttribute(gemm_tf32<2>, cudaFuncAttributeMaxDynamicSharedMemorySize, smem_bytes);
    cudaFuncSetAttribute(gemm_tf32<3>, cudaFuncAttributeMaxDynamicSharedMemorySize, smem_bytes);

    init_kernel<<<1, 32>>>();
    router_kernel<<<N_TOK, 256>>>(x, gw, sgw);

    // shared expert chain (MODE1 must write `out` before MODE3 atomics)
    gemm_tf32<0><<<dim3((2 * ISH) / BN, N_TOK / BM, 1), GT, smem_bytes>>>(x, swgu, nullptr, N_TOK, HID, 2 * ISH);
    {
        int total = N_TOK * (ISH / 4);
        silu_shared_kernel<<<(total + 255) / 256, 256>>>();
    }
    gemm_tf32<1><<<dim3(HID / BN, N_TOK / BM, 1), GT, smem_bytes>>>(nullptr, swd, out, N_TOK, ISH, HID);

    // routed experts (gathered), expert-down scatters atomically onto out
    gemm_tf32<2><<<dim3((2 * IMOE) / BN, N_TOK / BM, NEXP), GT, smem_bytes>>>(x, wgu, nullptr, N_TOK, HID, 2 * IMOE);
    {
        int total = NEXP * N_TOK * (IMOE / 4);
        silu_expert_kernel<<<(total + 255) / 256, 256>>>();
    }
    gemm_tf32<3><<<dim3(HID / BN, N_TOK / BM, NEXP), GT, smem_bytes>>>(nullptr, wd, out, N_TOK, IMOE, HID);
}

// round 4
// speedup vs baseline: 1.2690x; 1.2690x over previous
#include <cuda_runtime.h>
#include <cuda_fp16.h>
#include <cstdint>
#include <math.h>

#define N_TOK 1024
#define HID   2048
#define NEXP  8
#define IMOE  1408
#define ISH   5632

// ---------------- scratch (device globals; no allocation allowed) ----------------
__device__ float g_gu_s [(size_t)N_TOK * (2 * ISH)];        // shared gate_up out
__device__ float g_act_s[(size_t)N_TOK * ISH];              // shared activated
__device__ float g_gu_e [(size_t)NEXP * N_TOK * (2 * IMOE)];// expert gate_up out (compact)
__device__ float g_act_e[(size_t)NEXP * N_TOK * IMOE];      // expert activated (weighted)
__device__ float g_part [(size_t)N_TOK * 2 * HID];          // per-(token,slot) expert contribution
__device__ float g_sg  [N_TOK];                             // sigmoid shared gate
__device__ float g_wt  [NEXP * N_TOK];                      // routing weight per list entry
__device__ int   g_cnt [NEXP];
__device__ int   g_tok [NEXP * N_TOK];
__device__ int   g_slot[NEXP * N_TOK];

// ---------------- helpers ----------------
__device__ __forceinline__ float siluf(float v) { return v / (1.f + expf(-v)); }

__device__ __forceinline__ unsigned pk2(float x, float y) {
    __half2 h = __floats2half2_rn(make_float2(x, y).x ? x : x, y); // simple pack
    return *(unsigned*)&h;
}
__device__ __forceinline__ unsigned pack2(float x, float y) {
    __half2 h = __floats2half2_rn(x, y);
    return *(unsigned*)&h;
}

__device__ __forceinline__ void mma_f16(float* c, const unsigned* a, const unsigned* b) {
    asm volatile(
        "mma.sync.aligned.m16n8k16.row.col.f32.f16.f16.f32 "
        "{%0,%1,%2,%3}, {%4,%5,%6,%7}, {%8,%9}, {%0,%1,%2,%3};\n"
        : "+f"(c[0]), "+f"(c[1]), "+f"(c[2]), "+f"(c[3])
        : "r"(a[0]), "r"(a[1]), "r"(a[2]), "r"(a[3]), "r"(b[0]), "r"(b[1]));
}

// ---------------- init: zero per-expert counters (must run every replay) ----------------
__global__ void init_kernel() {
    if (threadIdx.x < NEXP) g_cnt[threadIdx.x] = 0;
}

// ---------------- router: logits, softmax, top-2, sigmoid shared gate ----------------
__global__ void router_kernel(const float* __restrict__ x,
                              const float* __restrict__ gate_w,
                              const float* __restrict__ sgate_w) {
    int n = blockIdx.x;
    int w = threadIdx.x >> 5, lane = threadIdx.x & 31;
    const float* xr = x + (size_t)n * HID;
    __shared__ float s_log[NEXP];
    __shared__ float s_sg;

    float acc = 0.f, accs = 0.f;
    for (int h = lane; h < HID; h += 32) {
        float xv = xr[h];
        acc += xv * gate_w[h * NEXP + w];
        if (w == 0) accs += xv * sgate_w[h];
    }
    #pragma unroll
    for (int o = 16; o > 0; o >>= 1) {
        acc  += __shfl_down_sync(0xffffffffu, acc, o);
        accs += __shfl_down_sync(0xffffffffu, accs, o);
    }
    if (lane == 0) { s_log[w] = acc; if (w == 0) s_sg = accs; }
    __syncthreads();

    if (threadIdx.x == 0) {
        float mx = s_log[0];
        #pragma unroll
        for (int e = 1; e < NEXP; e++) mx = fmaxf(mx, s_log[e]);
        float p[NEXP], den = 0.f;
        #pragma unroll
        for (int e = 0; e < NEXP; e++) { p[e] = expf(s_log[e] - mx); den += p[e]; }
        float inv = 1.f / den;
        #pragma unroll
        for (int e = 0; e < NEXP; e++) p[e] *= inv;
        int e0 = 0;
        #pragma unroll
        for (int e = 1; e < NEXP; e++) if (p[e] > p[e0]) e0 = e;
        int e1 = (e0 == 0) ? 1 : 0;
        #pragma unroll
        for (int e = 0; e < NEXP; e++) if (e != e0 && p[e] > p[e1]) e1 = e;
        int es[2] = {e0, e1};
        #pragma unroll
        for (int k = 0; k < 2; k++) {
            int e = es[k];
            int pos = atomicAdd(&g_cnt[e], 1);
            g_tok [e * N_TOK + pos] = n;
            g_slot[e * N_TOK + pos] = k;
            g_wt  [e * N_TOK + pos] = p[e];
        }
        g_sg[n] = 1.f / (1.f + expf(-s_sg));
    }
}

// ---------------- fp16 GEMM (fp32 accum), 128x128x32 tile, 256 threads ----------------
// MODE 0: g_gu_s = x @ swgu             MODE 1: out = act_s @ swd * sg[row]
// MODE 2: g_gu_e[e] = gather(x)@wgu[e]  MODE 3: g_part[tok,slot] = act_e[e]@wd[e]
#define BM 128
#define BN 128
#define BK 32
#define GT 256
#define APAD 8
#define A_LD (BK + APAD)   // 40 halves per row -> conflict-free frag loads

template<int MODE>
__global__ void __launch_bounds__(GT)
gemm_f16(const float* __restrict__ Ag, const float* __restrict__ Bg,
         float* __restrict__ Cg, int K, int N) {
    __shared__ __half As[2][BM][A_LD];   // K-major rows
    __shared__ __half Bs[2][BN][A_LD];   // N-major rows (K contiguous)

    const int tid  = threadIdx.x;
    const int lane = tid & 31, warp = tid >> 5;
    const int wm = warp & 1, wn = warp >> 1;      // 2x4 warp grid -> 64x32 warp tile
    const int g = lane >> 2, tg = lane & 3;

    const int m0 = blockIdx.y * BM;
    const int n0 = blockIdx.x * BN;
    const int e  = blockIdx.z;

    int Mrows = N_TOK;
    const float* B = Bg;
    if (MODE == 2 || MODE == 3) {
        Mrows = g_cnt[e];
        B = Bg + (size_t)e * (size_t)K * (size_t)N;
        if (m0 >= Mrows) return;
    }

    const float* Abase;
    if (MODE == 1)      Abase = g_act_s;
    else if (MODE == 3) Abase = g_act_e + (size_t)e * N_TOK * (size_t)K;
    else                Abase = Ag;

    // A loader: one row per two threads; thread covers 16 consecutive k floats
    const int ar = tid >> 1;               // 0..127
    const int kq = (tid & 1) * 16;         // 0 or 16
    const float* aP;
    {
        int rr = m0 + ar;
        if (MODE == 2) {
            int idx = (rr < Mrows) ? g_tok[e * N_TOK + rr] : 0;
            aP = Ag + (size_t)idx * (size_t)K;
        } else {
            if ((MODE == 3) && rr >= Mrows) rr = m0;   // clamp (discarded in epilogue)
            aP = Abase + (size_t)rr * (size_t)K;
        }
    }
    // B loader: one n-column per thread (two k-halves across tid>>7)
    const int bn  = tid & 127;
    const int bkq = (tid >> 7) * 16;       // 0 or 16
    const float* bP = B + n0 + bn;

    float acc[4][4][4];
    #pragma unroll
    for (int i = 0; i < 4; i++)
        #pragma unroll
        for (int j = 0; j < 4; j++)
            #pragma unroll
            for (int q = 0; q < 4; q++) acc[i][j][q] = 0.f;

    const int ktiles = K / BK;
    float4 av[4];
    float  bv[16];

    // ---- prologue: tile 0 -> buf 0 ----
    #pragma unroll
    for (int q = 0; q < 4; q++) av[q] = *(const float4*)(aP + kq + 4 * q);
    #pragma unroll
    for (int jj = 0; jj < 16; jj++) bv[jj] = bP[(size_t)(bkq + jj) * (size_t)N];
    {
        uint4 u0 = make_uint4(pack2(av[0].x, av[0].y), pack2(av[0].z, av[0].w),
                              pack2(av[1].x, av[1].y), pack2(av[1].z, av[1].w));
        uint4 u1 = make_uint4(pack2(av[2].x, av[2].y), pack2(av[2].z, av[2].w),
                              pack2(av[3].x, av[3].y), pack2(av[3].z, av[3].w));
        *(uint4*)&As[0][ar][kq]     = u0;
        *(uint4*)&As[0][ar][kq + 8] = u1;
        uint4 w0 = make_uint4(pack2(bv[0], bv[1]),   pack2(bv[2], bv[3]),
                              pack2(bv[4], bv[5]),   pack2(bv[6], bv[7]));
        uint4 w1 = make_uint4(pack2(bv[8], bv[9]),   pack2(bv[10], bv[11]),
                              pack2(bv[12], bv[13]), pack2(bv[14], bv[15]));
        *(uint4*)&Bs[0][bn][bkq]     = w0;
        *(uint4*)&Bs[0][bn][bkq + 8] = w1;
    }
    __syncthreads();

    for (int kt = 0; kt < ktiles; kt++) {
        const int buf = kt & 1;
        if (kt + 1 < ktiles) {
            const int k0 = (kt + 1) * BK;
            #pragma unroll
            for (int q = 0; q < 4; q++) av[q] = *(const float4*)(aP + k0 + kq + 4 * q);
            #pragma unroll
            for (int jj = 0; jj < 16; jj++) bv[jj] = bP[(size_t)(k0 + bkq + jj) * (size_t)N];
        }

        // ---- compute on buf: 2 k-steps of m16n8k16 ----
        #pragma unroll
        for (int ks = 0; ks < 2; ks++) {
            const int kk = ks * 16;
            unsigned af[4][4], bf[4][2];
            #pragma unroll
            for (int i = 0; i < 4; i++) {
                int r = wm * 64 + i * 16 + g;
                af[i][0] = *(const unsigned*)&As[buf][r    ][kk + 2 * tg];
                af[i][1] = *(const unsigned*)&As[buf][r + 8][kk + 2 * tg];
                af[i][2] = *(const unsigned*)&As[buf][r    ][kk + 2 * tg + 8];
                af[i][3] = *(const unsigned*)&As[buf][r + 8][kk + 2 * tg + 8];
            }
            #pragma unroll
            for (int j = 0; j < 4; j++) {
                int c = wn * 32 + j * 8 + g;
                bf[j][0] = *(const unsigned*)&Bs[buf][c][kk + 2 * tg];
                bf[j][1] = *(const unsigned*)&Bs[buf][c][kk + 2 * tg + 8];
            }
            #pragma unroll
            for (int i = 0; i < 4; i++)
                #pragma unroll
                for (int j = 0; j < 4; j++)
                    mma_f16(acc[i][j], af[i], bf[j]);
        }

        if (kt + 1 < ktiles) {
            const int nb = buf ^ 1;
            uint4 u0 = make_uint4(pack2(av[0].x, av[0].y), pack2(av[0].z, av[0].w),
                                  pack2(av[1].x, av[1].y), pack2(av[1].z, av[1].w));
            uint4 u1 = make_uint4(pack2(av[2].x, av[2].y), pack2(av[2].z, av[2].w),
                                  pack2(av[3].x, av[3].y), pack2(av[3].z, av[3].w));
            *(uint4*)&As[nb][ar][kq]     = u0;
            *(uint4*)&As[nb][ar][kq + 8] = u1;
            uint4 w0 = make_uint4(pack2(bv[0], bv[1]),   pack2(bv[2], bv[3]),
                                  pack2(bv[4], bv[5]),   pack2(bv[6], bv[7]));
            uint4 w1 = make_uint4(pack2(bv[8], bv[9]),   pack2(bv[10], bv[11]),
                                  pack2(bv[12], bv[13]), pack2(bv[14], bv[15]));
            *(uint4*)&Bs[nb][bn][bkq]     = w0;
            *(uint4*)&Bs[nb][bn][bkq + 8] = w1;
            __syncthreads();
        }
    }

    // ---- epilogue ----
    #pragma unroll
    for (int i = 0; i < 4; i++) {
        #pragma unroll
        for (int half = 0; half < 2; half++) {
            int lr = wm * 64 + i * 16 + g + half * 8;
            int gr = m0 + lr;
            if ((MODE == 2 || MODE == 3) && gr >= Mrows) continue;
            float* crow;
            float scale = 1.f;
            if (MODE == 0)      crow = g_gu_s + (size_t)gr * (size_t)N;
            else if (MODE == 1) { crow = Cg + (size_t)gr * (size_t)N; scale = g_sg[gr]; }
            else if (MODE == 2) crow = g_gu_e + ((size_t)e * N_TOK + gr) * (size_t)N;
            else {
                int t_ = g_tok [e * N_TOK + gr];
                int s_ = g_slot[e * N_TOK + gr];
                crow = g_part + ((size_t)t_ * 2 + s_) * (size_t)N;
            }
            #pragma unroll
            for (int j = 0; j < 4; j++) {
                int cc = n0 + wn * 32 + j * 8 + 2 * tg;
                float2 v = make_float2(acc[i][j][half * 2 + 0] * scale,
                                       acc[i][j][half * 2 + 1] * scale);
                *(float2*)(crow + cc) = v;
            }
        }
    }
}

// ---------------- elementwise: shared silu*up ----------------
__global__ void silu_shared_kernel() {
    int idx = blockIdx.x * blockDim.x + threadIdx.x;
    const int total = N_TOK * (ISH / 4);
    if (idx >= total) return;
    int n  = idx / (ISH / 4);
    int i4 = (idx % (ISH / 4)) * 4;
    const float* row = g_gu_s + (size_t)n * (2 * ISH);
    float4 gv = *(const float4*)(row + i4);
    float4 uv = *(const float4*)(row + ISH + i4);
    float4 o = make_float4(siluf(gv.x) * uv.x, siluf(gv.y) * uv.y,
                           siluf(gv.z) * uv.z, siluf(gv.w) * uv.w);
    *(float4*)(g_act_s + (size_t)n * ISH + i4) = o;
}

// ---------------- elementwise: expert silu*up, scaled by routing weight ----------------
__global__ void silu_expert_kernel() {
    int idx = blockIdx.x * blockDim.x + threadIdx.x;
    const int per = IMOE / 4;                 // 352
    const int total = NEXP * N_TOK * per;
    if (idx >= total) return;
    int e   = idx / (N_TOK * per);
    int rem = idx % (N_TOK * per);
    int m   = rem / per;
    int i4  = (rem % per) * 4;
    if (m >= g_cnt[e]) return;
    float w = g_wt[e * N_TOK + m];
    const float* row = g_gu_e + ((size_t)e * N_TOK + m) * (2 * IMOE);
    float4 gv = *(const float4*)(row + i4);
    float4 uv = *(const float4*)(row + IMOE + i4);
    float4 o = make_float4(w * siluf(gv.x) * uv.x, w * siluf(gv.y) * uv.y,
                           w * siluf(gv.z) * uv.z, w * siluf(gv.w) * uv.w);
    *(float4*)(g_act_e + ((size_t)e * N_TOK + m) * IMOE + i4) = o;
}

// ---------------- combine: out += part[slot0] + part[slot1] ----------------
__global__ void combine_kernel(float* __restrict__ out) {
    int idx = blockIdx.x * blockDim.x + threadIdx.x;
    const int total = N_TOK * (HID / 4);
    if (idx >= total) return;
    int n  = idx / (HID / 4);
    int h4 = (idx % (HID / 4)) * 4;
    float4 o  = *(float4*)(out + (size_t)n * HID + h4);
    float4 p0 = *(const float4*)(g_part + ((size_t)n * 2 + 0) * HID + h4);
    float4 p1 = *(const float4*)(g_part + ((size_t)n * 2 + 1) * HID + h4);
    o.x += p0.x + p1.x; o.y += p0.y + p1.y;
    o.z += p0.z + p1.z; o.w += p0.w + p1.w;
    *(float4*)(out + (size_t)n * HID + h4) = o;
}

// ---------------- launch ----------------
extern "C" void kernel_launch(void* const* d_in, const int* in_sizes, int n_in,
                              void* d_out, int out_size) {
    const float* x    = (const float*)d_in[0];   // [1024, 2048]
    const float* gw   = (const float*)d_in[1];   // [2048, 8]
    const float* wgu  = (const float*)d_in[2];   // [8, 2048, 2816]
    const float* wd   = (const float*)d_in[3];   // [8, 1408, 2048]
    const float* swgu = (const float*)d_in[4];   // [2048, 11264]
    const float* swd  = (const float*)d_in[5];   // [5632, 2048]
    const float* sgw  = (const float*)d_in[6];   // [2048, 1]
    float* out = (float*)d_out;                  // [1024, 2048]

    init_kernel<<<1, 32>>>();
    router_kernel<<<N_TOK, 256>>>(x, gw, sgw);

    // shared expert chain
    gemm_f16<0><<<dim3((2 * ISH) / BN, N_TOK / BM, 1), GT>>>(x, swgu, nullptr, HID, 2 * ISH);
    {
        int total = N_TOK * (ISH / 4);
        silu_shared_kernel<<<(total + 255) / 256, 256>>>();
    }
    gemm_f16<1><<<dim3(HID / BN, N_TOK / BM, 1), GT>>>(nullptr, swd, out, ISH, HID);

    // routed experts (gathered)
    gemm_f16<2><<<dim3((2 * IMOE) / BN, N_TOK / BM, NEXP), GT>>>(x, wgu, nullptr, HID, 2 * IMOE);
    {
        int total = NEXP * N_TOK * (IMOE / 4);
        silu_expert_kernel<<<(total + 255) / 256, 256>>>();
    }
    gemm_f16<3><<<dim3(HID / BN, N_TOK / BM, NEXP), GT>>>(nullptr, wd, nullptr, IMOE, HID);

    {
        int total = N_TOK * (HID / 4);
        combine_kernel<<<(total + 255) / 256, 256>>>(out);
    }
}

// round 5
// speedup vs baseline: 1.8965x; 1.4945x over previous
#include <cuda_runtime.h>
#include <cuda_fp16.h>
#include <cstdint>
#include <math.h>

#define N_TOK 1024
#define HID   2048
#define NEXP  8
#define IMOE  1408
#define ISH   5632

// ---------------- scratch (device globals; no allocation allowed) ----------------
__device__ float g_gu_s [(size_t)N_TOK * (2 * ISH)];         // shared gate_up out (fp32)
__device__ float g_gu_e [(size_t)NEXP * N_TOK * (2 * IMOE)]; // expert gate_up out (fp32, compact)
__device__ float g_part [(size_t)N_TOK * 2 * HID];           // per-(token,slot) expert contribution
__device__ float g_sg  [N_TOK];
__device__ float g_wt  [NEXP * N_TOK];
__device__ int   g_cnt [NEXP];
__device__ int   g_tok [NEXP * N_TOK];
__device__ int   g_slot[NEXP * N_TOK];

// fp16 operand mirrors
__device__ __half h_x    [(size_t)N_TOK * HID];
__device__ __half h_swgu [(size_t)HID * (2 * ISH)];
__device__ __half h_swd  [(size_t)ISH * HID];
__device__ __half h_wgu  [(size_t)NEXP * HID * (2 * IMOE)];
__device__ __half h_wd   [(size_t)NEXP * IMOE * HID];
__device__ __half h_act_s[(size_t)N_TOK * ISH];
__device__ __half h_act_e[(size_t)NEXP * N_TOK * IMOE];

// ---------------- helpers ----------------
__device__ __forceinline__ float siluf(float v) { return v / (1.f + expf(-v)); }

__device__ __forceinline__ void mma_f16(float* c, const unsigned* a, const unsigned* b) {
    asm volatile(
        "mma.sync.aligned.m16n8k16.row.col.f32.f16.f16.f32 "
        "{%0,%1,%2,%3}, {%4,%5,%6,%7}, {%8,%9}, {%0,%1,%2,%3};\n"
        : "+f"(c[0]), "+f"(c[1]), "+f"(c[2]), "+f"(c[3])
        : "r"(a[0]), "r"(a[1]), "r"(a[2]), "r"(a[3]), "r"(b[0]), "r"(b[1]));
}
__device__ __forceinline__ void ldsm_x4(unsigned* r, uint32_t a) {
    asm volatile("ldmatrix.sync.aligned.m8n8.x4.shared.b16 {%0,%1,%2,%3}, [%4];"
        : "=r"(r[0]), "=r"(r[1]), "=r"(r[2]), "=r"(r[3]) : "r"(a));
}
__device__ __forceinline__ void ldsm_x4_t(unsigned* r, uint32_t a) {
    asm volatile("ldmatrix.sync.aligned.m8n8.x4.trans.shared.b16 {%0,%1,%2,%3}, [%4];"
        : "=r"(r[0]), "=r"(r[1]), "=r"(r[2]), "=r"(r[3]) : "r"(a));
}
__device__ __forceinline__ void cp16(uint32_t dst, const void* src) {
    asm volatile("cp.async.cg.shared.global [%0], [%1], 16;\n" :: "r"(dst), "l"(src));
}
__device__ __forceinline__ void cp_commit() { asm volatile("cp.async.commit_group;\n"); }
template<int W> __device__ __forceinline__ void cp_wait() {
    asm volatile("cp.async.wait_group %0;\n" :: "n"(W));
}

// ---------------- fp32 -> fp16 streaming convert ----------------
// W: 0=x, 1=swgu, 2=swd, 3=wgu, 4=wd
template<int W>
__global__ void f2h_kernel(const float4* __restrict__ src, int n4) {
    int i = blockIdx.x * blockDim.x + threadIdx.x;
    if (i >= n4) return;
    __half* dst;
    if      (W == 0) dst = h_x;
    else if (W == 1) dst = h_swgu;
    else if (W == 2) dst = h_swd;
    else if (W == 3) dst = h_wgu;
    else             dst = h_wd;
    float4 v = src[i];
    __half2 h0 = __floats2half2_rn(v.x, v.y);
    __half2 h1 = __floats2half2_rn(v.z, v.w);
    uint2 u = make_uint2(*(unsigned*)&h0, *(unsigned*)&h1);
    *(uint2*)(dst + (size_t)i * 4) = u;
}

// ---------------- init ----------------
__global__ void init_kernel() {
    if (threadIdx.x < NEXP) g_cnt[threadIdx.x] = 0;
}

// ---------------- router ----------------
__global__ void router_kernel(const float* __restrict__ x,
                              const float* __restrict__ gate_w,
                              const float* __restrict__ sgate_w) {
    int n = blockIdx.x;
    int w = threadIdx.x >> 5, lane = threadIdx.x & 31;
    const float* xr = x + (size_t)n * HID;
    __shared__ float s_log[NEXP];
    __shared__ float s_sg;

    float acc = 0.f, accs = 0.f;
    for (int h = lane; h < HID; h += 32) {
        float xv = xr[h];
        acc += xv * gate_w[h * NEXP + w];
        if (w == 0) accs += xv * sgate_w[h];
    }
    #pragma unroll
    for (int o = 16; o > 0; o >>= 1) {
        acc  += __shfl_down_sync(0xffffffffu, acc, o);
        accs += __shfl_down_sync(0xffffffffu, accs, o);
    }
    if (lane == 0) { s_log[w] = acc; if (w == 0) s_sg = accs; }
    __syncthreads();

    if (threadIdx.x == 0) {
        float mx = s_log[0];
        #pragma unroll
        for (int e = 1; e < NEXP; e++) mx = fmaxf(mx, s_log[e]);
        float p[NEXP], den = 0.f;
        #pragma unroll
        for (int e = 0; e < NEXP; e++) { p[e] = expf(s_log[e] - mx); den += p[e]; }
        float inv = 1.f / den;
        #pragma unroll
        for (int e = 0; e < NEXP; e++) p[e] *= inv;
        int e0 = 0;
        #pragma unroll
        for (int e = 1; e < NEXP; e++) if (p[e] > p[e0]) e0 = e;
        int e1 = (e0 == 0) ? 1 : 0;
        #pragma unroll
        for (int e = 0; e < NEXP; e++) if (e != e0 && p[e] > p[e1]) e1 = e;
        int es[2] = {e0, e1};
        #pragma unroll
        for (int k = 0; k < 2; k++) {
            int e = es[k];
            int pos = atomicAdd(&g_cnt[e], 1);
            g_tok [e * N_TOK + pos] = n;
            g_slot[e * N_TOK + pos] = k;
            g_wt  [e * N_TOK + pos] = p[e];
        }
        g_sg[n] = 1.f / (1.f + expf(-s_sg));
    }
}

// ---------------- fp16 GEMM: 128x128x32, 256 thr, cp.async x4 stages, ldmatrix ----------------
// MODE 0: g_gu_s = h_x @ h_swgu              MODE 1: out = h_act_s @ h_swd * sg[row]
// MODE 2: g_gu_e[e] = gather(h_x) @ h_wgu[e] MODE 3: g_part[tok,slot] = h_act_e[e] @ h_wd[e]
#define BM 128
#define BN 128
#define BK 32
#define STAGES 4
#define A_PITCH 40          // halves per A row (80 B, 5*16B -> LDSM conflict-free)
#define B_PITCH 136         // halves per B k-row (272 B, 17*16B -> LDSM conflict-free)
#define A_BYTES (BM * A_PITCH * 2)   // 10240
#define B_BYTES (BK * B_PITCH * 2)   // 8704
#define STG_B   (A_BYTES + B_BYTES)  // 18944

template<int MODE>
__global__ void __launch_bounds__(256)
gemm_f16(float* __restrict__ Cg, int K, int N) {
    extern __shared__ __half smem[];

    const int tid  = threadIdx.x;
    const int lane = tid & 31, warp = tid >> 5;
    const int wm = warp & 1, wn = warp >> 1;       // 2x4 warps -> 64x32 warp tile

    const int m0 = blockIdx.y * BM;
    const int n0 = blockIdx.x * BN;
    const int e  = blockIdx.z;

    int Mrows = N_TOK;
    const __half *A, *B;
    if      (MODE == 0) { A = h_x;     B = h_swgu; }
    else if (MODE == 1) { A = h_act_s; B = h_swd;  }
    else if (MODE == 2) { Mrows = g_cnt[e]; A = h_x;
                          B = h_wgu + (size_t)e * HID * (2 * IMOE); }
    else                { Mrows = g_cnt[e];
                          A = h_act_e + (size_t)e * N_TOK * IMOE;
                          B = h_wd + (size_t)e * IMOE * HID; }
    if (m0 >= Mrows) return;

    // ---- cp.async loaders ----
    const int ar = tid >> 2, ac = (tid & 3) * 8;          // A rows ar, ar+64; 8-half chunk
    const __half *aP0, *aP1;
    {
        int r0 = m0 + ar, r1 = r0 + 64;
        if (MODE == 2) {
            int i0 = (r0 < Mrows) ? g_tok[e * N_TOK + r0] : 0;
            int i1 = (r1 < Mrows) ? g_tok[e * N_TOK + r1] : 0;
            aP0 = h_x + (size_t)i0 * HID;
            aP1 = h_x + (size_t)i1 * HID;
        } else {
            if (MODE == 3) { if (r0 >= Mrows) r0 = m0; if (r1 >= Mrows) r1 = m0; }
            aP0 = A + (size_t)r0 * K;
            aP1 = A + (size_t)r1 * K;
        }
    }
    const int bk = tid >> 4, bc = (tid & 15) * 8;         // B k-rows bk, bk+16
    const __half* bP = B + n0;

    const uint32_t sbase = (uint32_t)__cvta_generic_to_shared(smem);
    const uint32_t dA0 = sbase + (uint32_t)(ar * A_PITCH + ac) * 2u;
    const uint32_t dA1 = dA0 + 64u * A_PITCH * 2u;
    const uint32_t dB0 = sbase + (uint32_t)A_BYTES + (uint32_t)(bk * B_PITCH + bc) * 2u;
    const uint32_t dB1 = dB0 + 16u * B_PITCH * 2u;

    const int ktiles = K / BK;

    float acc[4][4][4];
    #pragma unroll
    for (int i = 0; i < 4; i++)
        #pragma unroll
        for (int j = 0; j < 4; j++)
            #pragma unroll
            for (int q = 0; q < 4; q++) acc[i][j][q] = 0.f;

    // ---- prologue: stages 0..2 ----
    #pragma unroll
    for (int s = 0; s < STAGES - 1; s++) {
        const int k0 = s * BK;
        const uint32_t so = (uint32_t)(s * STG_B);
        cp16(dA0 + so, aP0 + k0 + ac);
        cp16(dA1 + so, aP1 + k0 + ac);
        cp16(dB0 + so, bP + (size_t)(k0 + bk) * N + bc);
        cp16(dB1 + so, bP + (size_t)(k0 + bk + 16) * N + bc);
        cp_commit();
    }

    // ---- fragment lane addressing ----
    const int frow_l = (lane & 7) + ((lane >> 3) & 1) * 8;   // row within 16
    const int fhi_l  = (lane >> 4) & 1;                       // upper half selector
    const uint32_t aFragBase = sbase + (uint32_t)(((wm * 64 + frow_l) * A_PITCH) + fhi_l * 8) * 2u;
    const uint32_t bFragBase = sbase + (uint32_t)A_BYTES
                             + (uint32_t)((frow_l * B_PITCH) + wn * 32 + fhi_l * 8) * 2u;

    for (int kt = 0; kt < ktiles; kt++) {
        cp_wait<STAGES - 2>();
        __syncthreads();

        const int kn = kt + STAGES - 1;
        if (kn < ktiles) {
            const int k0 = kn * BK;
            const uint32_t so = (uint32_t)((kn & (STAGES - 1)) * STG_B);
            cp16(dA0 + so, aP0 + k0 + ac);
            cp16(dA1 + so, aP1 + k0 + ac);
            cp16(dB0 + so, bP + (size_t)(k0 + bk) * N + bc);
            cp16(dB1 + so, bP + (size_t)(k0 + bk + 16) * N + bc);
        }
        cp_commit();

        const uint32_t so = (uint32_t)((kt & (STAGES - 1)) * STG_B);
        #pragma unroll
        for (int ks = 0; ks < 2; ks++) {
            const int kk = ks * 16;
            unsigned af[4][4], bf[4][2];
            #pragma unroll
            for (int i = 0; i < 4; i++)
                ldsm_x4(af[i], aFragBase + so + (uint32_t)(i * 16 * A_PITCH + kk) * 2u);
            #pragma unroll
            for (int p = 0; p < 2; p++) {
                unsigned t[4];
                ldsm_x4_t(t, bFragBase + so + (uint32_t)(kk * B_PITCH + p * 16) * 2u);
                bf[2 * p    ][0] = t[0]; bf[2 * p    ][1] = t[1];
                bf[2 * p + 1][0] = t[2]; bf[2 * p + 1][1] = t[3];
            }
            #pragma unroll
            for (int i = 0; i < 4; i++)
                #pragma unroll
                for (int j = 0; j < 4; j++)
                    mma_f16(acc[i][j], af[i], bf[j]);
        }
    }

    // ---- epilogue ----
    const int g = lane >> 2, tg = lane & 3;
    #pragma unroll
    for (int i = 0; i < 4; i++) {
        #pragma unroll
        for (int half = 0; half < 2; half++) {
            int lr = wm * 64 + i * 16 + g + half * 8;
            int gr = m0 + lr;
            if ((MODE == 2 || MODE == 3) && gr >= Mrows) continue;
            float* crow;
            float scale = 1.f;
            if (MODE == 0)      crow = g_gu_s + (size_t)gr * (size_t)N;
            else if (MODE == 1) { crow = Cg + (size_t)gr * (size_t)N; scale = g_sg[gr]; }
            else if (MODE == 2) crow = g_gu_e + ((size_t)e * N_TOK + gr) * (size_t)N;
            else {
                int t_ = g_tok [e * N_TOK + gr];
                int s_ = g_slot[e * N_TOK + gr];
                crow = g_part + ((size_t)t_ * 2 + s_) * (size_t)N;
            }
            #pragma unroll
            for (int j = 0; j < 4; j++) {
                int cc = n0 + wn * 32 + j * 8 + 2 * tg;
                float2 v = make_float2(acc[i][j][half * 2 + 0] * scale,
                                       acc[i][j][half * 2 + 1] * scale);
                *(float2*)(crow + cc) = v;
            }
        }
    }
}

// ---------------- elementwise: shared silu*up -> fp16 ----------------
__global__ void silu_shared_kernel() {
    int idx = blockIdx.x * blockDim.x + threadIdx.x;
    const int total = N_TOK * (ISH / 4);
    if (idx >= total) return;
    int n  = idx / (ISH / 4);
    int i4 = (idx % (ISH / 4)) * 4;
    const float* row = g_gu_s + (size_t)n * (2 * ISH);
    float4 gv = *(const float4*)(row + i4);
    float4 uv = *(const float4*)(row + ISH + i4);
    __half2 h0 = __floats2half2_rn(siluf(gv.x) * uv.x, siluf(gv.y) * uv.y);
    __half2 h1 = __floats2half2_rn(siluf(gv.z) * uv.z, siluf(gv.w) * uv.w);
    uint2 u = make_uint2(*(unsigned*)&h0, *(unsigned*)&h1);
    *(uint2*)(h_act_s + (size_t)n * ISH + i4) = u;
}

// ---------------- elementwise: expert silu*up * route weight -> fp16 ----------------
__global__ void silu_expert_kernel() {
    int idx = blockIdx.x * blockDim.x + threadIdx.x;
    const int per = IMOE / 4;
    const int total = NEXP * N_TOK * per;
    if (idx >= total) return;
    int e   = idx / (N_TOK * per);
    int rem = idx % (N_TOK * per);
    int m   = rem / per;
    int i4  = (rem % per) * 4;
    if (m >= g_cnt[e]) return;
    float w = g_wt[e * N_TOK + m];
    const float* row = g_gu_e + ((size_t)e * N_TOK + m) * (2 * IMOE);
    float4 gv = *(const float4*)(row + i4);
    float4 uv = *(const float4*)(row + IMOE + i4);
    __half2 h0 = __floats2half2_rn(w * siluf(gv.x) * uv.x, w * siluf(gv.y) * uv.y);
    __half2 h1 = __floats2half2_rn(w * siluf(gv.z) * uv.z, w * siluf(gv.w) * uv.w);
    uint2 u = make_uint2(*(unsigned*)&h0, *(unsigned*)&h1);
    *(uint2*)(h_act_e + ((size_t)e * N_TOK + m) * IMOE + i4) = u;
}

// ---------------- combine ----------------
__global__ void combine_kernel(float* __restrict__ out) {
    int idx = blockIdx.x * blockDim.x + threadIdx.x;
    const int total = N_TOK * (HID / 4);
    if (idx >= total) return;
    int n  = idx / (HID / 4);
    int h4 = (idx % (HID / 4)) * 4;
    float4 o  = *(float4*)(out + (size_t)n * HID + h4);
    float4 p0 = *(const float4*)(g_part + ((size_t)n * 2 + 0) * HID + h4);
    float4 p1 = *(const float4*)(g_part + ((size_t)n * 2 + 1) * HID + h4);
    o.x += p0.x + p1.x; o.y += p0.y + p1.y;
    o.z += p0.z + p1.z; o.w += p0.w + p1.w;
    *(float4*)(out + (size_t)n * HID + h4) = o;
}

// ---------------- launch ----------------
extern "C" void kernel_launch(void* const* d_in, const int* in_sizes, int n_in,
                              void* d_out, int out_size) {
    const float* x    = (const float*)d_in[0];   // [1024, 2048]
    const float* gw   = (const float*)d_in[1];   // [2048, 8]
    const float* wgu  = (const float*)d_in[2];   // [8, 2048, 2816]
    const float* wd   = (const float*)d_in[3];   // [8, 1408, 2048]
    const float* swgu = (const float*)d_in[4];   // [2048, 11264]
    const float* swd  = (const float*)d_in[5];   // [5632, 2048]
    const float* sgw  = (const float*)d_in[6];   // [2048, 1]
    float* out = (float*)d_out;                  // [1024, 2048]

    const int smem_bytes = STAGES * STG_B;       // 75776
    cudaFuncSetAttribute(gemm_f16<0>, cudaFuncAttributeMaxDynamicSharedMemorySize, smem_bytes);
    cudaFuncSetAttribute(gemm_f16<1>, cudaFuncAttributeMaxDynamicSharedMemorySize, smem_bytes);
    cudaFuncSetAttribute(gemm_f16<2>, cudaFuncAttributeMaxDynamicSharedMemorySize, smem_bytes);
    cudaFuncSetAttribute(gemm_f16<3>, cudaFuncAttributeMaxDynamicSharedMemorySize, smem_bytes);

    init_kernel<<<1, 32>>>();
    router_kernel<<<N_TOK, 256>>>(x, gw, sgw);

    // fp32 -> fp16 conversions
    {
        int n4;
        n4 = (N_TOK * HID) / 4;
        f2h_kernel<0><<<(n4 + 255) / 256, 256>>>((const float4*)x, n4);
        n4 = (HID * 2 * ISH) / 4;
        f2h_kernel<1><<<(n4 + 255) / 256, 256>>>((const float4*)swgu, n4);
        n4 = (ISH * HID) / 4;
        f2h_kernel<2><<<(n4 + 255) / 256, 256>>>((const float4*)swd, n4);
        n4 = (NEXP * HID * 2 * IMOE) / 4;
        f2h_kernel<3><<<(n4 + 255) / 256, 256>>>((const float4*)wgu, n4);
        n4 = (NEXP * IMOE * HID) / 4;
        f2h_kernel<4><<<(n4 + 255) / 256, 256>>>((const float4*)wd, n4);
    }

    // shared expert chain
    gemm_f16<0><<<dim3((2 * ISH) / BN, N_TOK / BM, 1), 256, smem_bytes>>>(nullptr, HID, 2 * ISH);
    {
        int total = N_TOK * (ISH / 4);
        silu_shared_kernel<<<(total + 255) / 256, 256>>>();
    }
    gemm_f16<1><<<dim3(HID / BN, N_TOK / BM, 1), 256, smem_bytes>>>(out, ISH, HID);

    // routed experts (gathered)
    gemm_f16<2><<<dim3((2 * IMOE) / BN, N_TOK / BM, NEXP), 256, smem_bytes>>>(nullptr, HID, 2 * IMOE);
    {
        int total = NEXP * N_TOK * (IMOE / 4);
        silu_expert_kernel<<<(total + 255) / 256, 256>>>();
    }
    gemm_f16<3><<<dim3(HID / BN, N_TOK / BM, NEXP), 256, smem_bytes>>>(nullptr, IMOE, HID);

    {
        int total = N_TOK * (HID / 4);
        combine_kernel<<<(total + 255) / 256, 256>>>(out);
    }
}

// round 6
// speedup vs baseline: 1.9582x; 1.0326x over previous
#include <cuda_runtime.h>
#include <cuda_fp16.h>
#include <cstdint>
#include <math.h>

#define N_TOK 1024
#define HID   2048
#define NEXP  8
#define IMOE  1408
#define ISH   5632

// ---------------- scratch (device globals; no allocation allowed) ----------------
__device__ float g_part [(size_t)N_TOK * 2 * HID];           // per-(token,slot) expert contribution
__device__ float g_sg  [N_TOK];
__device__ float g_wt  [NEXP * N_TOK];
__device__ int   g_cnt [NEXP];
__device__ int   g_tok [NEXP * N_TOK];
__device__ int   g_slot[NEXP * N_TOK];

// fp16 operand mirrors
__device__ __half h_x    [(size_t)N_TOK * HID];
__device__ __half h_swgu [(size_t)HID * (2 * ISH)];
__device__ __half h_swd  [(size_t)ISH * HID];
__device__ __half h_wgu  [(size_t)NEXP * HID * (2 * IMOE)];
__device__ __half h_wd   [(size_t)NEXP * IMOE * HID];
__device__ __half h_act_s[(size_t)N_TOK * ISH];
__device__ __half h_act_e[(size_t)NEXP * N_TOK * IMOE];

// ---------------- helpers ----------------
__device__ __forceinline__ float siluf(float v) { return v / (1.f + expf(-v)); }

__device__ __forceinline__ void mma_f16(float* c, const unsigned* a, const unsigned* b) {
    asm volatile(
        "mma.sync.aligned.m16n8k16.row.col.f32.f16.f16.f32 "
        "{%0,%1,%2,%3}, {%4,%5,%6,%7}, {%8,%9}, {%0,%1,%2,%3};\n"
        : "+f"(c[0]), "+f"(c[1]), "+f"(c[2]), "+f"(c[3])
        : "r"(a[0]), "r"(a[1]), "r"(a[2]), "r"(a[3]), "r"(b[0]), "r"(b[1]));
}
__device__ __forceinline__ void ldsm_x4(unsigned* r, uint32_t a) {
    asm volatile("ldmatrix.sync.aligned.m8n8.x4.shared.b16 {%0,%1,%2,%3}, [%4];"
        : "=r"(r[0]), "=r"(r[1]), "=r"(r[2]), "=r"(r[3]) : "r"(a));
}
__device__ __forceinline__ void ldsm_x4_t(unsigned* r, uint32_t a) {
    asm volatile("ldmatrix.sync.aligned.m8n8.x4.trans.shared.b16 {%0,%1,%2,%3}, [%4];"
        : "=r"(r[0]), "=r"(r[1]), "=r"(r[2]), "=r"(r[3]) : "r"(a));
}
__device__ __forceinline__ void cp16(uint32_t dst, const void* src) {
    asm volatile("cp.async.cg.shared.global [%0], [%1], 16;\n" :: "r"(dst), "l"(src));
}
__device__ __forceinline__ void cp_commit() { asm volatile("cp.async.commit_group;\n"); }
template<int W> __device__ __forceinline__ void cp_wait() {
    asm volatile("cp.async.wait_group %0;\n" :: "n"(W));
}

// ---------------- fp32 -> fp16 streaming convert (2 float4 per thread) ----------------
// W: 1=swgu, 2=swd, 3=wgu, 4=wd
template<int W>
__global__ void f2h_kernel(const float4* __restrict__ src, int n8) {
    int i = blockIdx.x * blockDim.x + threadIdx.x;
    if (i >= n8) return;
    __half* dst;
    if      (W == 1) dst = h_swgu;
    else if (W == 2) dst = h_swd;
    else if (W == 3) dst = h_wgu;
    else             dst = h_wd;
    float4 v0 = src[2 * i];
    float4 v1 = src[2 * i + 1];
    __half2 a = __floats2half2_rn(v0.x, v0.y);
    __half2 b = __floats2half2_rn(v0.z, v0.w);
    __half2 c = __floats2half2_rn(v1.x, v1.y);
    __half2 d = __floats2half2_rn(v1.z, v1.w);
    uint4 u = make_uint4(*(unsigned*)&a, *(unsigned*)&b, *(unsigned*)&c, *(unsigned*)&d);
    *(uint4*)(dst + (size_t)i * 8) = u;
}

// ---------------- init ----------------
__global__ void init_kernel() {
    if (threadIdx.x < NEXP) g_cnt[threadIdx.x] = 0;
}

// ---------------- router (also emits h_x) ----------------
__global__ void router_kernel(const float* __restrict__ x,
                              const float* __restrict__ gate_w,
                              const float* __restrict__ sgate_w) {
    int n = blockIdx.x;
    int w = threadIdx.x >> 5, lane = threadIdx.x & 31;
    const float* xr = x + (size_t)n * HID;
    __shared__ float s_log[NEXP];
    __shared__ float s_sg;

    float acc = 0.f, accs = 0.f;
    for (int h = lane; h < HID; h += 32) {
        float xv = xr[h];
        acc += xv * gate_w[h * NEXP + w];
        if (w == 0) { accs += xv * sgate_w[h]; h_x[(size_t)n * HID + h] = __float2half(xv); }
    }
    #pragma unroll
    for (int o = 16; o > 0; o >>= 1) {
        acc  += __shfl_down_sync(0xffffffffu, acc, o);
        accs += __shfl_down_sync(0xffffffffu, accs, o);
    }
    if (lane == 0) { s_log[w] = acc; if (w == 0) s_sg = accs; }
    __syncthreads();

    if (threadIdx.x == 0) {
        float mx = s_log[0];
        #pragma unroll
        for (int e = 1; e < NEXP; e++) mx = fmaxf(mx, s_log[e]);
        float p[NEXP], den = 0.f;
        #pragma unroll
        for (int e = 0; e < NEXP; e++) { p[e] = expf(s_log[e] - mx); den += p[e]; }
        float inv = 1.f / den;
        #pragma unroll
        for (int e = 0; e < NEXP; e++) p[e] *= inv;
        int e0 = 0;
        #pragma unroll
        for (int e = 1; e < NEXP; e++) if (p[e] > p[e0]) e0 = e;
        int e1 = (e0 == 0) ? 1 : 0;
        #pragma unroll
        for (int e = 0; e < NEXP; e++) if (e != e0 && p[e] > p[e1]) e1 = e;
        int es[2] = {e0, e1};
        #pragma unroll
        for (int k = 0; k < 2; k++) {
            int e = es[k];
            int pos = atomicAdd(&g_cnt[e], 1);
            g_tok [e * N_TOK + pos] = n;
            g_slot[e * N_TOK + pos] = k;
            g_wt  [e * N_TOK + pos] = p[e];
        }
        g_sg[n] = 1.f / (1.f + expf(-s_sg));
    }
}

// =======================================================================================
// Tiling constants (shared by both GEMM kernels)
#define BM 128
#define BN 128
#define BK 32
#define A_PITCH 40
#define B_PITCH 136
#define A_BYTES (BM * A_PITCH * 2)   // 10240
#define B_BYTES (BK * B_PITCH * 2)   // 8704

// ---------------- FUSED gate_up GEMM + SiLU*up -> fp16 act ----------------
// MODE 0: h_act_s = silu(h_x@Wg) * (h_x@Wu)            (shared expert)
// MODE 2: h_act_e[e] = w * silu(gather@Wg[e]) * (gather@Wu[e])
#define FSTAGES 3
#define FSTG_B  (A_BYTES + 2 * B_BYTES)   // 27648

template<int MODE>
__global__ void __launch_bounds__(256)
gemm_gu(int K, int Nb, int Iact) {
    extern __shared__ __half smem[];

    const int tid  = threadIdx.x;
    const int lane = tid & 31, warp = tid >> 5;
    const int wm = warp & 1, wn = warp >> 1;

    const int m0 = blockIdx.y * BM;
    const int n0 = blockIdx.x * BN;           // column within [0, Iact)
    const int e  = blockIdx.z;

    int Mrows = N_TOK;
    const __half* B;
    if (MODE == 0) B = h_swgu;
    else { Mrows = g_cnt[e]; B = h_wgu + (size_t)e * HID * (2 * IMOE); }
    if (m0 >= Mrows) return;

    // ---- cp.async loaders ----
    const int ar = tid >> 2, ac = (tid & 3) * 8;
    const __half *aP0, *aP1;
    {
        int r0 = m0 + ar, r1 = r0 + 64;
        if (MODE == 2) {
            int i0 = (r0 < Mrows) ? g_tok[e * N_TOK + r0] : 0;
            int i1 = (r1 < Mrows) ? g_tok[e * N_TOK + r1] : 0;
            aP0 = h_x + (size_t)i0 * HID;
            aP1 = h_x + (size_t)i1 * HID;
        } else {
            aP0 = h_x + (size_t)r0 * HID;
            aP1 = h_x + (size_t)r1 * HID;
        }
    }
    const int bk = tid >> 4, bc = (tid & 15) * 8;
    const __half* bPg = B + n0;               // gate columns
    const __half* bPu = B + Iact + n0;        // up columns

    const uint32_t sbase = (uint32_t)__cvta_generic_to_shared(smem);
    const uint32_t dA0 = sbase + (uint32_t)(ar * A_PITCH + ac) * 2u;
    const uint32_t dA1 = dA0 + 64u * A_PITCH * 2u;
    const uint32_t dG0 = sbase + (uint32_t)A_BYTES + (uint32_t)(bk * B_PITCH + bc) * 2u;
    const uint32_t dG1 = dG0 + 16u * B_PITCH * 2u;
    const uint32_t dU0 = dG0 + (uint32_t)B_BYTES;
    const uint32_t dU1 = dG1 + (uint32_t)B_BYTES;

    const int ktiles = K / BK;

    float accg[4][4][4], accu[4][4][4];
    #pragma unroll
    for (int i = 0; i < 4; i++)
        #pragma unroll
        for (int j = 0; j < 4; j++)
            #pragma unroll
            for (int q = 0; q < 4; q++) { accg[i][j][q] = 0.f; accu[i][j][q] = 0.f; }

    // prologue
    #pragma unroll
    for (int s = 0; s < FSTAGES - 1; s++) {
        const int k0 = s * BK;
        const uint32_t so = (uint32_t)(s * FSTG_B);
        cp16(dA0 + so, aP0 + k0 + ac);
        cp16(dA1 + so, aP1 + k0 + ac);
        cp16(dG0 + so, bPg + (size_t)(k0 + bk) * Nb + bc);
        cp16(dG1 + so, bPg + (size_t)(k0 + bk + 16) * Nb + bc);
        cp16(dU0 + so, bPu + (size_t)(k0 + bk) * Nb + bc);
        cp16(dU1 + so, bPu + (size_t)(k0 + bk + 16) * Nb + bc);
        cp_commit();
    }

    const int frow_l = (lane & 7) + ((lane >> 3) & 1) * 8;
    const int fhi_l  = (lane >> 4) & 1;
    const uint32_t aFrag = sbase + (uint32_t)(((wm * 64 + frow_l) * A_PITCH) + fhi_l * 8) * 2u;
    const uint32_t gFrag = sbase + (uint32_t)A_BYTES
                         + (uint32_t)((frow_l * B_PITCH) + wn * 32 + fhi_l * 8) * 2u;

    for (int kt = 0; kt < ktiles; kt++) {
        cp_wait<FSTAGES - 2>();
        __syncthreads();

        const int kn = kt + FSTAGES - 1;
        if (kn < ktiles) {
            const int k0 = kn * BK;
            const uint32_t so = (uint32_t)((kn % FSTAGES) * FSTG_B);
            cp16(dA0 + so, aP0 + k0 + ac);
            cp16(dA1 + so, aP1 + k0 + ac);
            cp16(dG0 + so, bPg + (size_t)(k0 + bk) * Nb + bc);
            cp16(dG1 + so, bPg + (size_t)(k0 + bk + 16) * Nb + bc);
            cp16(dU0 + so, bPu + (size_t)(k0 + bk) * Nb + bc);
            cp16(dU1 + so, bPu + (size_t)(k0 + bk + 16) * Nb + bc);
        }
        cp_commit();

        const uint32_t so = (uint32_t)((kt % FSTAGES) * FSTG_B);
        #pragma unroll
        for (int ks = 0; ks < 2; ks++) {
            const int kk = ks * 16;
            unsigned af[4][4], bg[4][2], bu[4][2];
            #pragma unroll
            for (int i = 0; i < 4; i++)
                ldsm_x4(af[i], aFrag + so + (uint32_t)(i * 16 * A_PITCH + kk) * 2u);
            #pragma unroll
            for (int p = 0; p < 2; p++) {
                unsigned t[4];
                ldsm_x4_t(t, gFrag + so + (uint32_t)(kk * B_PITCH + p * 16) * 2u);
                bg[2 * p][0] = t[0]; bg[2 * p][1] = t[1];
                bg[2 * p + 1][0] = t[2]; bg[2 * p + 1][1] = t[3];
                ldsm_x4_t(t, gFrag + so + (uint32_t)B_BYTES + (uint32_t)(kk * B_PITCH + p * 16) * 2u);
                bu[2 * p][0] = t[0]; bu[2 * p][1] = t[1];
                bu[2 * p + 1][0] = t[2]; bu[2 * p + 1][1] = t[3];
            }
            #pragma unroll
            for (int i = 0; i < 4; i++)
                #pragma unroll
                for (int j = 0; j < 4; j++) {
                    mma_f16(accg[i][j], af[i], bg[j]);
                    mma_f16(accu[i][j], af[i], bu[j]);
                }
        }
    }

    // ---- fused epilogue: act = [w*] silu(gate) * up -> fp16 ----
    const int g = lane >> 2, tg = lane & 3;
    #pragma unroll
    for (int i = 0; i < 4; i++) {
        #pragma unroll
        for (int half = 0; half < 2; half++) {
            int lr = wm * 64 + i * 16 + g + half * 8;
            int gr = m0 + lr;
            if (MODE == 2 && gr >= Mrows) continue;
            __half* arow;
            float w = 1.f;
            if (MODE == 0) arow = h_act_s + (size_t)gr * Iact;
            else {
                w = g_wt[e * N_TOK + gr];
                arow = h_act_e + ((size_t)e * N_TOK + gr) * Iact;
            }
            #pragma unroll
            for (int j = 0; j < 4; j++) {
                int cc = n0 + wn * 32 + j * 8 + 2 * tg;
                float v0 = w * siluf(accg[i][j][half * 2 + 0]) * accu[i][j][half * 2 + 0];
                float v1 = w * siluf(accg[i][j][half * 2 + 1]) * accu[i][j][half * 2 + 1];
                __half2 hv = __floats2half2_rn(v0, v1);
                *(__half2*)(arow + cc) = hv;
            }
        }
    }
}

// ---------------- down-proj GEMM (modes 1 and 3), 4-stage ----------------
// MODE 1: out = h_act_s @ h_swd * sg[row]
// MODE 3: g_part[tok,slot] = h_act_e[e] @ h_wd[e]
#define STAGES 4
#define STG_B (A_BYTES + B_BYTES)   // 18944

template<int MODE>
__global__ void __launch_bounds__(256)
gemm_dn(float* __restrict__ Cg, int K, int N) {
    extern __shared__ __half smem[];

    const int tid  = threadIdx.x;
    const int lane = tid & 31, warp = tid >> 5;
    const int wm = warp & 1, wn = warp >> 1;

    const int m0 = blockIdx.y * BM;
    const int n0 = blockIdx.x * BN;
    const int e  = blockIdx.z;

    int Mrows = N_TOK;
    const __half *A, *B;
    if (MODE == 1) { A = h_act_s; B = h_swd; }
    else {
        Mrows = g_cnt[e];
        A = h_act_e + (size_t)e * N_TOK * IMOE;
        B = h_wd + (size_t)e * IMOE * HID;
    }
    if (m0 >= Mrows) return;

    const int ar = tid >> 2, ac = (tid & 3) * 8;
    const __half *aP0, *aP1;
    {
        int r0 = m0 + ar, r1 = r0 + 64;
        if (MODE == 3) { if (r0 >= Mrows) r0 = m0; if (r1 >= Mrows) r1 = m0; }
        aP0 = A + (size_t)r0 * K;
        aP1 = A + (size_t)r1 * K;
    }
    const int bk = tid >> 4, bc = (tid & 15) * 8;
    const __half* bP = B + n0;

    const uint32_t sbase = (uint32_t)__cvta_generic_to_shared(smem);
    const uint32_t dA0 = sbase + (uint32_t)(ar * A_PITCH + ac) * 2u;
    const uint32_t dA1 = dA0 + 64u * A_PITCH * 2u;
    const uint32_t dB0 = sbase + (uint32_t)A_BYTES + (uint32_t)(bk * B_PITCH + bc) * 2u;
    const uint32_t dB1 = dB0 + 16u * B_PITCH * 2u;

    const int ktiles = K / BK;

    float acc[4][4][4];
    #pragma unroll
    for (int i = 0; i < 4; i++)
        #pragma unroll
        for (int j = 0; j < 4; j++)
            #pragma unroll
            for (int q = 0; q < 4; q++) acc[i][j][q] = 0.f;

    #pragma unroll
    for (int s = 0; s < STAGES - 1; s++) {
        const int k0 = s * BK;
        const uint32_t so = (uint32_t)(s * STG_B);
        cp16(dA0 + so, aP0 + k0 + ac);
        cp16(dA1 + so, aP1 + k0 + ac);
        cp16(dB0 + so, bP + (size_t)(k0 + bk) * N + bc);
        cp16(dB1 + so, bP + (size_t)(k0 + bk + 16) * N + bc);
        cp_commit();
    }

    const int frow_l = (lane & 7) + ((lane >> 3) & 1) * 8;
    const int fhi_l  = (lane >> 4) & 1;
    const uint32_t aFrag = sbase + (uint32_t)(((wm * 64 + frow_l) * A_PITCH) + fhi_l * 8) * 2u;
    const uint32_t bFrag = sbase + (uint32_t)A_BYTES
                         + (uint32_t)((frow_l * B_PITCH) + wn * 32 + fhi_l * 8) * 2u;

    for (int kt = 0; kt < ktiles; kt++) {
        cp_wait<STAGES - 2>();
        __syncthreads();

        const int kn = kt + STAGES - 1;
        if (kn < ktiles) {
            const int k0 = kn * BK;
            const uint32_t so = (uint32_t)((kn & (STAGES - 1)) * STG_B);
            cp16(dA0 + so, aP0 + k0 + ac);
            cp16(dA1 + so, aP1 + k0 + ac);
            cp16(dB0 + so, bP + (size_t)(k0 + bk) * N + bc);
            cp16(dB1 + so, bP + (size_t)(k0 + bk + 16) * N + bc);
        }
        cp_commit();

        const uint32_t so = (uint32_t)((kt & (STAGES - 1)) * STG_B);
        #pragma unroll
        for (int ks = 0; ks < 2; ks++) {
            const int kk = ks * 16;
            unsigned af[4][4], bf[4][2];
            #pragma unroll
            for (int i = 0; i < 4; i++)
                ldsm_x4(af[i], aFrag + so + (uint32_t)(i * 16 * A_PITCH + kk) * 2u);
            #pragma unroll
            for (int p = 0; p < 2; p++) {
                unsigned t[4];
                ldsm_x4_t(t, bFrag + so + (uint32_t)(kk * B_PITCH + p * 16) * 2u);
                bf[2 * p][0] = t[0]; bf[2 * p][1] = t[1];
                bf[2 * p + 1][0] = t[2]; bf[2 * p + 1][1] = t[3];
            }
            #pragma unroll
            for (int i = 0; i < 4; i++)
                #pragma unroll
                for (int j = 0; j < 4; j++)
                    mma_f16(acc[i][j], af[i], bf[j]);
        }
    }

    const int g = lane >> 2, tg = lane & 3;
    #pragma unroll
    for (int i = 0; i < 4; i++) {
        #pragma unroll
        for (int half = 0; half < 2; half++) {
            int lr = wm * 64 + i * 16 + g + half * 8;
            int gr = m0 + lr;
            if (MODE == 3 && gr >= Mrows) continue;
            float* crow;
            float scale = 1.f;
            if (MODE == 1) { crow = Cg + (size_t)gr * (size_t)N; scale = g_sg[gr]; }
            else {
                int t_ = g_tok [e * N_TOK + gr];
                int s_ = g_slot[e * N_TOK + gr];
                crow = g_part + ((size_t)t_ * 2 + s_) * (size_t)N;
            }
            #pragma unroll
            for (int j = 0; j < 4; j++) {
                int cc = n0 + wn * 32 + j * 8 + 2 * tg;
                float2 v = make_float2(acc[i][j][half * 2 + 0] * scale,
                                       acc[i][j][half * 2 + 1] * scale);
                *(float2*)(crow + cc) = v;
            }
        }
    }
}

// ---------------- combine ----------------
__global__ void combine_kernel(float* __restrict__ out) {
    int idx = blockIdx.x * blockDim.x + threadIdx.x;
    const int total = N_TOK * (HID / 4);
    if (idx >= total) return;
    int n  = idx / (HID / 4);
    int h4 = (idx % (HID / 4)) * 4;
    float4 o  = *(float4*)(out + (size_t)n * HID + h4);
    float4 p0 = *(const float4*)(g_part + ((size_t)n * 2 + 0) * HID + h4);
    float4 p1 = *(const float4*)(g_part + ((size_t)n * 2 + 1) * HID + h4);
    o.x += p0.x + p1.x; o.y += p0.y + p1.y;
    o.z += p0.z + p1.z; o.w += p0.w + p1.w;
    *(float4*)(out + (size_t)n * HID + h4) = o;
}

// ---------------- launch ----------------
extern "C" void kernel_launch(void* const* d_in, const int* in_sizes, int n_in,
                              void* d_out, int out_size) {
    const float* x    = (const float*)d_in[0];
    const float* gw   = (const float*)d_in[1];
    const float* wgu  = (const float*)d_in[2];
    const float* wd   = (const float*)d_in[3];
    const float* swgu = (const float*)d_in[4];
    const float* swd  = (const float*)d_in[5];
    const float* sgw  = (const float*)d_in[6];
    float* out = (float*)d_out;

    const int fsmem = FSTAGES * FSTG_B;   // 82944
    const int dsmem = STAGES * STG_B;     // 75776
    cudaFuncSetAttribute(gemm_gu<0>, cudaFuncAttributeMaxDynamicSharedMemorySize, fsmem);
    cudaFuncSetAttribute(gemm_gu<2>, cudaFuncAttributeMaxDynamicSharedMemorySize, fsmem);
    cudaFuncSetAttribute(gemm_dn<1>, cudaFuncAttributeMaxDynamicSharedMemorySize, dsmem);
    cudaFuncSetAttribute(gemm_dn<3>, cudaFuncAttributeMaxDynamicSharedMemorySize, dsmem);

    // launches ordered so #6 (ncu capture point) is the big fused GEMM
    {
        int n8;
        n8 = (HID * 2 * ISH) / 8;
        f2h_kernel<1><<<(n8 + 255) / 256, 256>>>((const float4*)swgu, n8);   // 1
        n8 = (NEXP * HID * 2 * IMOE) / 8;
        f2h_kernel<3><<<(n8 + 255) / 256, 256>>>((const float4*)wgu, n8);    // 2
        n8 = (NEXP * IMOE * HID) / 8;
        f2h_kernel<4><<<(n8 + 255) / 256, 256>>>((const float4*)wd, n8);     // 3
    }
    init_kernel<<<1, 32>>>();                                                // 4
    router_kernel<<<N_TOK, 256>>>(x, gw, sgw);                               // 5

    // shared expert gate_up + silu (fused)                                  // 6 <- profiled
    gemm_gu<0><<<dim3(ISH / BN, N_TOK / BM, 1), 256, fsmem>>>(HID, 2 * ISH, ISH);

    {
        int n8 = (ISH * HID) / 8;
        f2h_kernel<2><<<(n8 + 255) / 256, 256>>>((const float4*)swd, n8);    // 7
    }

    // shared expert down (writes out with sigmoid gate)
    gemm_dn<1><<<dim3(HID / BN, N_TOK / BM, 1), 256, dsmem>>>(out, ISH, HID);

    // routed experts: fused gate_up+silu, then down into g_part
    gemm_gu<2><<<dim3(IMOE / BN, N_TOK / BM, NEXP), 256, fsmem>>>(HID, 2 * IMOE, IMOE);
    gemm_dn<3><<<dim3(HID / BN, N_TOK / BM, NEXP), 256, dsmem>>>(nullptr, IMOE, HID);

    {
        int total = N_TOK * (HID / 4);
        combine_kernel<<<(total + 255) / 256, 256>>>(out);
    }
}

// round 7
// speedup vs baseline: 2.2773x; 1.1629x over previous
#include <cuda_runtime.h>
#include <cuda_fp16.h>
#include <cstdint>
#include <math.h>

#define N_TOK 1024
#define HID   2048
#define NEXP  8
#define IMOE  1408
#define ISH   5632

// ---------------- scratch (device globals; no allocation allowed) ----------------
__device__ float g_part [(size_t)N_TOK * 2 * HID];           // per-(token,slot) expert contribution
__device__ float g_sg  [N_TOK];
__device__ float g_wt  [NEXP * N_TOK];
__device__ int   g_cnt [NEXP];
__device__ int   g_tok [NEXP * N_TOK];
__device__ int   g_slot[NEXP * N_TOK];

// fp16 operand mirrors
__device__ __half h_x    [(size_t)N_TOK * HID];
__device__ __half h_swgu [(size_t)HID * (2 * ISH)];
__device__ __half h_swd  [(size_t)ISH * HID];
__device__ __half h_wgu  [(size_t)NEXP * HID * (2 * IMOE)];
__device__ __half h_wd   [(size_t)NEXP * IMOE * HID];
__device__ __half h_act_s[(size_t)N_TOK * ISH];
__device__ __half h_act_e[(size_t)NEXP * N_TOK * IMOE];

// ---------------- helpers ----------------
__device__ __forceinline__ float siluf(float v) { return v / (1.f + expf(-v)); }

__device__ __forceinline__ void mma_f16(float* c, const unsigned* a, const unsigned* b) {
    asm volatile(
        "mma.sync.aligned.m16n8k16.row.col.f32.f16.f16.f32 "
        "{%0,%1,%2,%3}, {%4,%5,%6,%7}, {%8,%9}, {%0,%1,%2,%3};\n"
        : "+f"(c[0]), "+f"(c[1]), "+f"(c[2]), "+f"(c[3])
        : "r"(a[0]), "r"(a[1]), "r"(a[2]), "r"(a[3]), "r"(b[0]), "r"(b[1]));
}
__device__ __forceinline__ void ldsm_x4(unsigned* r, uint32_t a) {
    asm volatile("ldmatrix.sync.aligned.m8n8.x4.shared.b16 {%0,%1,%2,%3}, [%4];"
        : "=r"(r[0]), "=r"(r[1]), "=r"(r[2]), "=r"(r[3]) : "r"(a));
}
__device__ __forceinline__ void ldsm_x4_t(unsigned* r, uint32_t a) {
    asm volatile("ldmatrix.sync.aligned.m8n8.x4.trans.shared.b16 {%0,%1,%2,%3}, [%4];"
        : "=r"(r[0]), "=r"(r[1]), "=r"(r[2]), "=r"(r[3]) : "r"(a));
}
__device__ __forceinline__ void cp16(uint32_t dst, const void* src) {
    asm volatile("cp.async.cg.shared.global [%0], [%1], 16;\n" :: "r"(dst), "l"(src));
}
__device__ __forceinline__ void cp_commit() { asm volatile("cp.async.commit_group;\n"); }
template<int W> __device__ __forceinline__ void cp_wait() {
    asm volatile("cp.async.wait_group %0;\n" :: "n"(W));
}

// ---------------- fp32 -> fp16 streaming convert (2 float4 per thread) ----------------
// W: 1=swgu, 2=swd, 3=wgu, 4=wd
template<int W>
__global__ void f2h_kernel(const float4* __restrict__ src, int n8) {
    int i = blockIdx.x * blockDim.x + threadIdx.x;
    if (i >= n8) return;
    __half* dst;
    if      (W == 1) dst = h_swgu;
    else if (W == 2) dst = h_swd;
    else if (W == 3) dst = h_wgu;
    else             dst = h_wd;
    float4 v0 = src[2 * i];
    float4 v1 = src[2 * i + 1];
    __half2 a = __floats2half2_rn(v0.x, v0.y);
    __half2 b = __floats2half2_rn(v0.z, v0.w);
    __half2 c = __floats2half2_rn(v1.x, v1.y);
    __half2 d = __floats2half2_rn(v1.z, v1.w);
    uint4 u = make_uint4(*(unsigned*)&a, *(unsigned*)&b, *(unsigned*)&c, *(unsigned*)&d);
    *(uint4*)(dst + (size_t)i * 8) = u;
}

// ---------------- init ----------------
__global__ void init_kernel() {
    if (threadIdx.x < NEXP) g_cnt[threadIdx.x] = 0;
}

// ---------------- router (also emits h_x) ----------------
__global__ void router_kernel(const float* __restrict__ x,
                              const float* __restrict__ gate_w,
                              const float* __restrict__ sgate_w) {
    int n = blockIdx.x;
    int w = threadIdx.x >> 5, lane = threadIdx.x & 31;
    const float* xr = x + (size_t)n * HID;
    __shared__ float s_log[NEXP];
    __shared__ float s_sg;

    float acc = 0.f, accs = 0.f;
    for (int h = lane; h < HID; h += 32) {
        float xv = xr[h];
        acc += xv * gate_w[h * NEXP + w];
        if (w == 0) { accs += xv * sgate_w[h]; h_x[(size_t)n * HID + h] = __float2half(xv); }
    }
    #pragma unroll
    for (int o = 16; o > 0; o >>= 1) {
        acc  += __shfl_down_sync(0xffffffffu, acc, o);
        accs += __shfl_down_sync(0xffffffffu, accs, o);
    }
    if (lane == 0) { s_log[w] = acc; if (w == 0) s_sg = accs; }
    __syncthreads();

    if (threadIdx.x == 0) {
        float mx = s_log[0];
        #pragma unroll
        for (int e = 1; e < NEXP; e++) mx = fmaxf(mx, s_log[e]);
        float p[NEXP], den = 0.f;
        #pragma unroll
        for (int e = 0; e < NEXP; e++) { p[e] = expf(s_log[e] - mx); den += p[e]; }
        float inv = 1.f / den;
        #pragma unroll
        for (int e = 0; e < NEXP; e++) p[e] *= inv;
        int e0 = 0;
        #pragma unroll
        for (int e = 1; e < NEXP; e++) if (p[e] > p[e0]) e0 = e;
        int e1 = (e0 == 0) ? 1 : 0;
        #pragma unroll
        for (int e = 0; e < NEXP; e++) if (e != e0 && p[e] > p[e1]) e1 = e;
        int es[2] = {e0, e1};
        #pragma unroll
        for (int k = 0; k < 2; k++) {
            int e = es[k];
            int pos = atomicAdd(&g_cnt[e], 1);
            g_tok [e * N_TOK + pos] = n;
            g_slot[e * N_TOK + pos] = k;
            g_wt  [e * N_TOK + pos] = p[e];
        }
        g_sg[n] = 1.f / (1.f + expf(-s_sg));
    }
}

// =======================================================================================
#define BM 128
#define BN 128
#define BK 32
#define A_PITCH 40
#define B_PITCH 136
#define A_BYTES (BM * A_PITCH * 2)   // 10240
#define B_BYTES (BK * B_PITCH * 2)   // 8704

// ---------------- FUSED gate_up GEMM + SiLU*up -> fp16 act ----------------
#define FSTAGES 3
#define FSTG_B  (A_BYTES + 2 * B_BYTES)   // 27648

template<int MODE>
__global__ void __launch_bounds__(256)
gemm_gu(int K, int Nb, int Iact) {
    extern __shared__ __half smem[];

    const int tid  = threadIdx.x;
    const int lane = tid & 31, warp = tid >> 5;
    const int wm = warp & 1, wn = warp >> 1;

    const int m0 = blockIdx.y * BM;
    const int n0 = blockIdx.x * BN;
    const int e  = blockIdx.z;

    int Mrows = N_TOK;
    const __half* B;
    if (MODE == 0) B = h_swgu;
    else { Mrows = g_cnt[e]; B = h_wgu + (size_t)e * HID * (2 * IMOE); }
    if (m0 >= Mrows) return;

    const int ar = tid >> 2, ac = (tid & 3) * 8;
    const __half *aP0, *aP1;
    {
        int r0 = m0 + ar, r1 = r0 + 64;
        if (MODE == 2) {
            int i0 = (r0 < Mrows) ? g_tok[e * N_TOK + r0] : 0;
            int i1 = (r1 < Mrows) ? g_tok[e * N_TOK + r1] : 0;
            aP0 = h_x + (size_t)i0 * HID;
            aP1 = h_x + (size_t)i1 * HID;
        } else {
            aP0 = h_x + (size_t)r0 * HID;
            aP1 = h_x + (size_t)r1 * HID;
        }
    }
    const int bk = tid >> 4, bc = (tid & 15) * 8;
    const __half* bPg = B + n0;
    const __half* bPu = B + Iact + n0;

    const uint32_t sbase = (uint32_t)__cvta_generic_to_shared(smem);
    const uint32_t dA0 = sbase + (uint32_t)(ar * A_PITCH + ac) * 2u;
    const uint32_t dA1 = dA0 + 64u * A_PITCH * 2u;
    const uint32_t dG0 = sbase + (uint32_t)A_BYTES + (uint32_t)(bk * B_PITCH + bc) * 2u;
    const uint32_t dG1 = dG0 + 16u * B_PITCH * 2u;
    const uint32_t dU0 = dG0 + (uint32_t)B_BYTES;
    const uint32_t dU1 = dG1 + (uint32_t)B_BYTES;

    const int ktiles = K / BK;

    float accg[4][4][4], accu[4][4][4];
    #pragma unroll
    for (int i = 0; i < 4; i++)
        #pragma unroll
        for (int j = 0; j < 4; j++)
            #pragma unroll
            for (int q = 0; q < 4; q++) { accg[i][j][q] = 0.f; accu[i][j][q] = 0.f; }

    #pragma unroll
    for (int s = 0; s < FSTAGES - 1; s++) {
        const int k0 = s * BK;
        const uint32_t so = (uint32_t)(s * FSTG_B);
        cp16(dA0 + so, aP0 + k0 + ac);
        cp16(dA1 + so, aP1 + k0 + ac);
        cp16(dG0 + so, bPg + (size_t)(k0 + bk) * Nb + bc);
        cp16(dG1 + so, bPg + (size_t)(k0 + bk + 16) * Nb + bc);
        cp16(dU0 + so, bPu + (size_t)(k0 + bk) * Nb + bc);
        cp16(dU1 + so, bPu + (size_t)(k0 + bk + 16) * Nb + bc);
        cp_commit();
    }

    const int frow_l = (lane & 7) + ((lane >> 3) & 1) * 8;
    const int fhi_l  = (lane >> 4) & 1;
    const uint32_t aFrag = sbase + (uint32_t)(((wm * 64 + frow_l) * A_PITCH) + fhi_l * 8) * 2u;
    const uint32_t gFrag = sbase + (uint32_t)A_BYTES
                         + (uint32_t)((frow_l * B_PITCH) + wn * 32 + fhi_l * 8) * 2u;

    for (int kt = 0; kt < ktiles; kt++) {
        cp_wait<FSTAGES - 2>();
        __syncthreads();

        const int kn = kt + FSTAGES - 1;
        if (kn < ktiles) {
            const int k0 = kn * BK;
            const uint32_t so = (uint32_t)((kn % FSTAGES) * FSTG_B);
            cp16(dA0 + so, aP0 + k0 + ac);
            cp16(dA1 + so, aP1 + k0 + ac);
            cp16(dG0 + so, bPg + (size_t)(k0 + bk) * Nb + bc);
            cp16(dG1 + so, bPg + (size_t)(k0 + bk + 16) * Nb + bc);
            cp16(dU0 + so, bPu + (size_t)(k0 + bk) * Nb + bc);
            cp16(dU1 + so, bPu + (size_t)(k0 + bk + 16) * Nb + bc);
        }
        cp_commit();

        const uint32_t so = (uint32_t)((kt % FSTAGES) * FSTG_B);
        #pragma unroll
        for (int ks = 0; ks < 2; ks++) {
            const int kk = ks * 16;
            unsigned af[4][4], bg[4][2], bu[4][2];
            #pragma unroll
            for (int i = 0; i < 4; i++)
                ldsm_x4(af[i], aFrag + so + (uint32_t)(i * 16 * A_PITCH + kk) * 2u);
            #pragma unroll
            for (int p = 0; p < 2; p++) {
                unsigned t[4];
                ldsm_x4_t(t, gFrag + so + (uint32_t)(kk * B_PITCH + p * 16) * 2u);
                bg[2 * p][0] = t[0]; bg[2 * p][1] = t[1];
                bg[2 * p + 1][0] = t[2]; bg[2 * p + 1][1] = t[3];
                ldsm_x4_t(t, gFrag + so + (uint32_t)B_BYTES + (uint32_t)(kk * B_PITCH + p * 16) * 2u);
                bu[2 * p][0] = t[0]; bu[2 * p][1] = t[1];
                bu[2 * p + 1][0] = t[2]; bu[2 * p + 1][1] = t[3];
            }
            #pragma unroll
            for (int i = 0; i < 4; i++)
                #pragma unroll
                for (int j = 0; j < 4; j++) {
                    mma_f16(accg[i][j], af[i], bg[j]);
                    mma_f16(accu[i][j], af[i], bu[j]);
                }
        }
    }

    const int g = lane >> 2, tg = lane & 3;
    #pragma unroll
    for (int i = 0; i < 4; i++) {
        #pragma unroll
        for (int half = 0; half < 2; half++) {
            int lr = wm * 64 + i * 16 + g + half * 8;
            int gr = m0 + lr;
            if (MODE == 2 && gr >= Mrows) continue;
            __half* arow;
            float w = 1.f;
            if (MODE == 0) arow = h_act_s + (size_t)gr * Iact;
            else {
                w = g_wt[e * N_TOK + gr];
                arow = h_act_e + ((size_t)e * N_TOK + gr) * Iact;
            }
            #pragma unroll
            for (int j = 0; j < 4; j++) {
                int cc = n0 + wn * 32 + j * 8 + 2 * tg;
                float v0 = w * siluf(accg[i][j][half * 2 + 0]) * accu[i][j][half * 2 + 0];
                float v1 = w * siluf(accg[i][j][half * 2 + 1]) * accu[i][j][half * 2 + 1];
                __half2 hv = __floats2half2_rn(v0, v1);
                *(__half2*)(arow + cc) = hv;
            }
        }
    }
}

// ---------------- down-proj GEMM ----------------
#define STAGES 4
#define STG_B (A_BYTES + B_BYTES)   // 18944

template<int MODE>
__global__ void __launch_bounds__(256)
gemm_dn(float* __restrict__ Cg, int K, int N) {
    extern __shared__ __half smem[];

    const int tid  = threadIdx.x;
    const int lane = tid & 31, warp = tid >> 5;
    const int wm = warp & 1, wn = warp >> 1;

    const int m0 = blockIdx.y * BM;
    const int n0 = blockIdx.x * BN;
    const int e  = blockIdx.z;

    int Mrows = N_TOK;
    const __half *A, *B;
    if (MODE == 1) { A = h_act_s; B = h_swd; }
    else {
        Mrows = g_cnt[e];
        A = h_act_e + (size_t)e * N_TOK * IMOE;
        B = h_wd + (size_t)e * IMOE * HID;
    }
    if (m0 >= Mrows) return;

    const int ar = tid >> 2, ac = (tid & 3) * 8;
    const __half *aP0, *aP1;
    {
        int r0 = m0 + ar, r1 = r0 + 64;
        if (MODE == 3) { if (r0 >= Mrows) r0 = m0; if (r1 >= Mrows) r1 = m0; }
        aP0 = A + (size_t)r0 * K;
        aP1 = A + (size_t)r1 * K;
    }
    const int bk = tid >> 4, bc = (tid & 15) * 8;
    const __half* bP = B + n0;

    const uint32_t sbase = (uint32_t)__cvta_generic_to_shared(smem);
    const uint32_t dA0 = sbase + (uint32_t)(ar * A_PITCH + ac) * 2u;
    const uint32_t dA1 = dA0 + 64u * A_PITCH * 2u;
    const uint32_t dB0 = sbase + (uint32_t)A_BYTES + (uint32_t)(bk * B_PITCH + bc) * 2u;
    const uint32_t dB1 = dB0 + 16u * B_PITCH * 2u;

    const int ktiles = K / BK;

    float acc[4][4][4];
    #pragma unroll
    for (int i = 0; i < 4; i++)
        #pragma unroll
        for (int j = 0; j < 4; j++)
            #pragma unroll
            for (int q = 0; q < 4; q++) acc[i][j][q] = 0.f;

    #pragma unroll
    for (int s = 0; s < STAGES - 1; s++) {
        const int k0 = s * BK;
        const uint32_t so = (uint32_t)(s * STG_B);
        cp16(dA0 + so, aP0 + k0 + ac);
        cp16(dA1 + so, aP1 + k0 + ac);
        cp16(dB0 + so, bP + (size_t)(k0 + bk) * N + bc);
        cp16(dB1 + so, bP + (size_t)(k0 + bk + 16) * N + bc);
        cp_commit();
    }

    const int frow_l = (lane & 7) + ((lane >> 3) & 1) * 8;
    const int fhi_l  = (lane >> 4) & 1;
    const uint32_t aFrag = sbase + (uint32_t)(((wm * 64 + frow_l) * A_PITCH) + fhi_l * 8) * 2u;
    const uint32_t bFrag = sbase + (uint32_t)A_BYTES
                         + (uint32_t)((frow_l * B_PITCH) + wn * 32 + fhi_l * 8) * 2u;

    for (int kt = 0; kt < ktiles; kt++) {
        cp_wait<STAGES - 2>();
        __syncthreads();

        const int kn = kt + STAGES - 1;
        if (kn < ktiles) {
            const int k0 = kn * BK;
            const uint32_t so = (uint32_t)((kn & (STAGES - 1)) * STG_B);
            cp16(dA0 + so, aP0 + k0 + ac);
            cp16(dA1 + so, aP1 + k0 + ac);
            cp16(dB0 + so, bP + (size_t)(k0 + bk) * N + bc);
            cp16(dB1 + so, bP + (size_t)(k0 + bk + 16) * N + bc);
        }
        cp_commit();

        const uint32_t so = (uint32_t)((kt & (STAGES - 1)) * STG_B);
        #pragma unroll
        for (int ks = 0; ks < 2; ks++) {
            const int kk = ks * 16;
            unsigned af[4][4], bf[4][2];
            #pragma unroll
            for (int i = 0; i < 4; i++)
                ldsm_x4(af[i], aFrag + so + (uint32_t)(i * 16 * A_PITCH + kk) * 2u);
            #pragma unroll
            for (int p = 0; p < 2; p++) {
                unsigned t[4];
                ldsm_x4_t(t, bFrag + so + (uint32_t)(kk * B_PITCH + p * 16) * 2u);
                bf[2 * p][0] = t[0]; bf[2 * p][1] = t[1];
                bf[2 * p + 1][0] = t[2]; bf[2 * p + 1][1] = t[3];
            }
            #pragma unroll
            for (int i = 0; i < 4; i++)
                #pragma unroll
                for (int j = 0; j < 4; j++)
                    mma_f16(acc[i][j], af[i], bf[j]);
        }
    }

    const int g = lane >> 2, tg = lane & 3;
    #pragma unroll
    for (int i = 0; i < 4; i++) {
        #pragma unroll
        for (int half = 0; half < 2; half++) {
            int lr = wm * 64 + i * 16 + g + half * 8;
            int gr = m0 + lr;
            if (MODE == 3 && gr >= Mrows) continue;
            float* crow;
            float scale = 1.f;
            if (MODE == 1) { crow = Cg + (size_t)gr * (size_t)N; scale = g_sg[gr]; }
            else {
                int t_ = g_tok [e * N_TOK + gr];
                int s_ = g_slot[e * N_TOK + gr];
                crow = g_part + ((size_t)t_ * 2 + s_) * (size_t)N;
            }
            #pragma unroll
            for (int j = 0; j < 4; j++) {
                int cc = n0 + wn * 32 + j * 8 + 2 * tg;
                float2 v = make_float2(acc[i][j][half * 2 + 0] * scale,
                                       acc[i][j][half * 2 + 1] * scale);
                *(float2*)(crow + cc) = v;
            }
        }
    }
}

// ---------------- combine ----------------
__global__ void combine_kernel(float* __restrict__ out) {
    int idx = blockIdx.x * blockDim.x + threadIdx.x;
    const int total = N_TOK * (HID / 4);
    if (idx >= total) return;
    int n  = idx / (HID / 4);
    int h4 = (idx % (HID / 4)) * 4;
    float4 o  = *(float4*)(out + (size_t)n * HID + h4);
    float4 p0 = *(const float4*)(g_part + ((size_t)n * 2 + 0) * HID + h4);
    float4 p1 = *(const float4*)(g_part + ((size_t)n * 2 + 1) * HID + h4);
    o.x += p0.x + p1.x; o.y += p0.y + p1.y;
    o.z += p0.z + p1.z; o.w += p0.w + p1.w;
    *(float4*)(out + (size_t)n * HID + h4) = o;
}

// ---------------- launch (multi-stream overlap; capturable via event fork/join) ----------------
extern "C" void kernel_launch(void* const* d_in, const int* in_sizes, int n_in,
                              void* d_out, int out_size) {
    const float* x    = (const float*)d_in[0];
    const float* gw   = (const float*)d_in[1];
    const float* wgu  = (const float*)d_in[2];
    const float* wd   = (const float*)d_in[3];
    const float* swgu = (const float*)d_in[4];
    const float* swd  = (const float*)d_in[5];
    const float* sgw  = (const float*)d_in[6];
    float* out = (float*)d_out;

    static cudaStream_t s1 = nullptr, s2 = nullptr;
    static cudaEvent_t ev_fork = nullptr, ev_wgu = nullptr, ev_wd = nullptr,
                       ev_swd = nullptr, ev_rt = nullptr, ev_exp = nullptr;
    if (s1 == nullptr) {
        cudaStreamCreateWithFlags(&s1, cudaStreamNonBlocking);
        cudaStreamCreateWithFlags(&s2, cudaStreamNonBlocking);
        cudaEventCreateWithFlags(&ev_fork, cudaEventDisableTiming);
        cudaEventCreateWithFlags(&ev_wgu,  cudaEventDisableTiming);
        cudaEventCreateWithFlags(&ev_wd,   cudaEventDisableTiming);
        cudaEventCreateWithFlags(&ev_swd,  cudaEventDisableTiming);
        cudaEventCreateWithFlags(&ev_rt,   cudaEventDisableTiming);
        cudaEventCreateWithFlags(&ev_exp,  cudaEventDisableTiming);
    }

    const int fsmem = FSTAGES * FSTG_B;   // 82944
    const int dsmem = STAGES * STG_B;     // 75776
    cudaFuncSetAttribute(gemm_gu<0>, cudaFuncAttributeMaxDynamicSharedMemorySize, fsmem);
    cudaFuncSetAttribute(gemm_gu<2>, cudaFuncAttributeMaxDynamicSharedMemorySize, fsmem);
    cudaFuncSetAttribute(gemm_dn<1>, cudaFuncAttributeMaxDynamicSharedMemorySize, dsmem);
    cudaFuncSetAttribute(gemm_dn<3>, cudaFuncAttributeMaxDynamicSharedMemorySize, dsmem);

    // ---- fork side streams off the capture-origin stream (stream 0) ----
    init_kernel<<<1, 32>>>();
    cudaEventRecord(ev_fork, 0);
    cudaStreamWaitEvent(s1, ev_fork, 0);
    cudaStreamWaitEvent(s2, ev_fork, 0);

    // s1: big weight converts (memory-bound; overlap with GEMMs on stream 0)
    {
        int n8 = (NEXP * HID * 2 * IMOE) / 8;
        f2h_kernel<3><<<(n8 + 255) / 256, 256, 0, s1>>>((const float4*)wgu, n8);
        cudaEventRecord(ev_wgu, s1);
        n8 = (NEXP * IMOE * HID) / 8;
        f2h_kernel<4><<<(n8 + 255) / 256, 256, 0, s1>>>((const float4*)wd, n8);
        cudaEventRecord(ev_wd, s1);
        n8 = (ISH * HID) / 8;
        f2h_kernel<2><<<(n8 + 255) / 256, 256, 0, s1>>>((const float4*)swd, n8);
        cudaEventRecord(ev_swd, s1);
    }

    // stream 0: shared-expert chain
    {
        int n8 = (HID * 2 * ISH) / 8;
        f2h_kernel<1><<<(n8 + 255) / 256, 256>>>((const float4*)swgu, n8);
    }
    router_kernel<<<N_TOK, 256>>>(x, gw, sgw);
    cudaEventRecord(ev_rt, 0);

    gemm_gu<0><<<dim3(ISH / BN, N_TOK / BM, 1), 256, fsmem>>>(HID, 2 * ISH, ISH);
    cudaStreamWaitEvent(0, ev_swd, 0);
    gemm_dn<1><<<dim3(HID / BN, N_TOK / BM, 1), 256, dsmem>>>(out, ISH, HID);

    // s2: routed-expert chain (needs router + wgu / wd converts)
    cudaStreamWaitEvent(s2, ev_rt, 0);
    cudaStreamWaitEvent(s2, ev_wgu, 0);
    gemm_gu<2><<<dim3(IMOE / BN, N_TOK / BM, NEXP), 256, fsmem, s2>>>(HID, 2 * IMOE, IMOE);
    cudaStreamWaitEvent(s2, ev_wd, 0);
    gemm_dn<3><<<dim3(HID / BN, N_TOK / BM, NEXP), 256, dsmem, s2>>>(nullptr, IMOE, HID);
    cudaEventRecord(ev_exp, s2);

    // join: combine on stream 0 after both chains
    cudaStreamWaitEvent(0, ev_exp, 0);
    {
        int total = N_TOK * (HID / 4);
        combine_kernel<<<(total + 255) / 256, 256>>>(out);
    }
}

// round 8
// speedup vs baseline: 2.3343x; 1.0250x over previous
#include <cuda_runtime.h>
#include <cuda_fp16.h>
#include <cstdint>
#include <math.h>

#define N_TOK 1024
#define HID   2048
#define NEXP  8
#define IMOE  1408
#define ISH   5632

// ---------------- scratch (device globals; no allocation allowed) ----------------
__device__ float g_part [(size_t)N_TOK * 2 * HID];
__device__ float g_sg  [N_TOK];
__device__ float g_wt  [NEXP * N_TOK];
__device__ int   g_cnt [NEXP];
__device__ int   g_tok [NEXP * N_TOK];
__device__ int   g_slot[NEXP * N_TOK];

// fp16 operand mirrors
__device__ __half h_x    [(size_t)N_TOK * HID];
__device__ __half h_swgu [(size_t)HID * (2 * ISH)];
__device__ __half h_swd  [(size_t)ISH * HID];
__device__ __half h_wgu  [(size_t)NEXP * HID * (2 * IMOE)];
__device__ __half h_wd   [(size_t)NEXP * IMOE * HID];
__device__ __half h_act_s[(size_t)N_TOK * ISH];
__device__ __half h_act_e[(size_t)NEXP * N_TOK * IMOE];

// ---------------- helpers ----------------
__device__ __forceinline__ float siluf(float v) { return v / (1.f + expf(-v)); }

__device__ __forceinline__ void mma_f16(float* c, const unsigned* a, const unsigned* b) {
    asm volatile(
        "mma.sync.aligned.m16n8k16.row.col.f32.f16.f16.f32 "
        "{%0,%1,%2,%3}, {%4,%5,%6,%7}, {%8,%9}, {%0,%1,%2,%3};\n"
        : "+f"(c[0]), "+f"(c[1]), "+f"(c[2]), "+f"(c[3])
        : "r"(a[0]), "r"(a[1]), "r"(a[2]), "r"(a[3]), "r"(b[0]), "r"(b[1]));
}
__device__ __forceinline__ void ldsm_x4(unsigned* r, uint32_t a) {
    asm volatile("ldmatrix.sync.aligned.m8n8.x4.shared.b16 {%0,%1,%2,%3}, [%4];"
        : "=r"(r[0]), "=r"(r[1]), "=r"(r[2]), "=r"(r[3]) : "r"(a));
}
__device__ __forceinline__ void ldsm_x4_t(unsigned* r, uint32_t a) {
    asm volatile("ldmatrix.sync.aligned.m8n8.x4.trans.shared.b16 {%0,%1,%2,%3}, [%4];"
        : "=r"(r[0]), "=r"(r[1]), "=r"(r[2]), "=r"(r[3]) : "r"(a));
}
__device__ __forceinline__ void cp16(uint32_t dst, const void* src) {
    asm volatile("cp.async.cg.shared.global [%0], [%1], 16;\n" :: "r"(dst), "l"(src));
}
__device__ __forceinline__ void cp_commit() { asm volatile("cp.async.commit_group;\n"); }
template<int W> __device__ __forceinline__ void cp_wait() {
    asm volatile("cp.async.wait_group %0;\n" :: "n"(W));
}

// ---------------- fp32 -> fp16 streaming convert ----------------
// W: 1=swgu, 2=swd, 3=wgu, 4=wd
template<int W>
__global__ void f2h_kernel(const float4* __restrict__ src, int n8) {
    int i = blockIdx.x * blockDim.x + threadIdx.x;
    if (i >= n8) return;
    __half* dst;
    if      (W == 1) dst = h_swgu;
    else if (W == 2) dst = h_swd;
    else if (W == 3) dst = h_wgu;
    else             dst = h_wd;
    float4 v0 = src[2 * i];
    float4 v1 = src[2 * i + 1];
    __half2 a = __floats2half2_rn(v0.x, v0.y);
    __half2 b = __floats2half2_rn(v0.z, v0.w);
    __half2 c = __floats2half2_rn(v1.x, v1.y);
    __half2 d = __floats2half2_rn(v1.z, v1.w);
    uint4 u = make_uint4(*(unsigned*)&a, *(unsigned*)&b, *(unsigned*)&c, *(unsigned*)&d);
    *(uint4*)(dst + (size_t)i * 8) = u;
}

// ---------------- init ----------------
__global__ void init_kernel() {
    if (threadIdx.x < NEXP) g_cnt[threadIdx.x] = 0;
}

// ---------------- router (also emits h_x) ----------------
__global__ void router_kernel(const float* __restrict__ x,
                              const float* __restrict__ gate_w,
                              const float* __restrict__ sgate_w) {
    int n = blockIdx.x;
    int w = threadIdx.x >> 5, lane = threadIdx.x & 31;
    const float* xr = x + (size_t)n * HID;
    __shared__ float s_log[NEXP];
    __shared__ float s_sg;

    float acc = 0.f, accs = 0.f;
    for (int h = lane; h < HID; h += 32) {
        float xv = xr[h];
        acc += xv * gate_w[h * NEXP + w];
        if (w == 0) { accs += xv * sgate_w[h]; h_x[(size_t)n * HID + h] = __float2half(xv); }
    }
    #pragma unroll
    for (int o = 16; o > 0; o >>= 1) {
        acc  += __shfl_down_sync(0xffffffffu, acc, o);
        accs += __shfl_down_sync(0xffffffffu, accs, o);
    }
    if (lane == 0) { s_log[w] = acc; if (w == 0) s_sg = accs; }
    __syncthreads();

    if (threadIdx.x == 0) {
        float mx = s_log[0];
        #pragma unroll
        for (int e = 1; e < NEXP; e++) mx = fmaxf(mx, s_log[e]);
        float p[NEXP], den = 0.f;
        #pragma unroll
        for (int e = 0; e < NEXP; e++) { p[e] = expf(s_log[e] - mx); den += p[e]; }
        float inv = 1.f / den;
        #pragma unroll
        for (int e = 0; e < NEXP; e++) p[e] *= inv;
        int e0 = 0;
        #pragma unroll
        for (int e = 1; e < NEXP; e++) if (p[e] > p[e0]) e0 = e;
        int e1 = (e0 == 0) ? 1 : 0;
        #pragma unroll
        for (int e = 0; e < NEXP; e++) if (e != e0 && p[e] > p[e1]) e1 = e;
        int es[2] = {e0, e1};
        #pragma unroll
        for (int k = 0; k < 2; k++) {
            int e = es[k];
            int pos = atomicAdd(&g_cnt[e], 1);
            g_tok [e * N_TOK + pos] = n;
            g_slot[e * N_TOK + pos] = k;
            g_wt  [e * N_TOK + pos] = p[e];
        }
        g_sg[n] = 1.f / (1.f + expf(-s_sg));
    }
}

// =======================================================================================
#define BM 128
#define BN 128
#define BK 32
#define A_PITCH 40
#define B_PITCH 136
#define A_BYTES (BM * A_PITCH * 2)   // 10240
#define B_BYTES (BK * B_PITCH * 2)   // 8704

// ---------------- FUSED gate_up GEMM + SiLU*up -> fp16 act ----------------
#define FSTAGES 3
#define FSTG_B  (A_BYTES + 2 * B_BYTES)   // 27648

template<int MODE>
__global__ void __launch_bounds__(256)
gemm_gu(int K, int Nb, int Iact, int n_base) {
    extern __shared__ __half smem[];

    const int tid  = threadIdx.x;
    const int lane = tid & 31, warp = tid >> 5;
    const int wm = warp & 1, wn = warp >> 1;

    const int m0 = blockIdx.y * BM;
    const int n0 = n_base + blockIdx.x * BN;
    const int e  = blockIdx.z;

    int Mrows = N_TOK;
    const __half* B;
    if (MODE == 0) B = h_swgu;
    else { Mrows = g_cnt[e]; B = h_wgu + (size_t)e * HID * (2 * IMOE); }
    if (m0 >= Mrows) return;

    const int ar = tid >> 2, ac = (tid & 3) * 8;
    const __half *aP0, *aP1;
    {
        int r0 = m0 + ar, r1 = r0 + 64;
        if (MODE == 2) {
            int i0 = (r0 < Mrows) ? g_tok[e * N_TOK + r0] : 0;
            int i1 = (r1 < Mrows) ? g_tok[e * N_TOK + r1] : 0;
            aP0 = h_x + (size_t)i0 * HID;
            aP1 = h_x + (size_t)i1 * HID;
        } else {
            aP0 = h_x + (size_t)r0 * HID;
            aP1 = h_x + (size_t)r1 * HID;
        }
    }
    const int bk = tid >> 4, bc = (tid & 15) * 8;
    const __half* bPg = B + n0;
    const __half* bPu = B + Iact + n0;

    const uint32_t sbase = (uint32_t)__cvta_generic_to_shared(smem);
    const uint32_t dA0 = sbase + (uint32_t)(ar * A_PITCH + ac) * 2u;
    const uint32_t dA1 = dA0 + 64u * A_PITCH * 2u;
    const uint32_t dG0 = sbase + (uint32_t)A_BYTES + (uint32_t)(bk * B_PITCH + bc) * 2u;
    const uint32_t dG1 = dG0 + 16u * B_PITCH * 2u;
    const uint32_t dU0 = dG0 + (uint32_t)B_BYTES;
    const uint32_t dU1 = dG1 + (uint32_t)B_BYTES;

    const int ktiles = K / BK;

    float accg[4][4][4], accu[4][4][4];
    #pragma unroll
    for (int i = 0; i < 4; i++)
        #pragma unroll
        for (int j = 0; j < 4; j++)
            #pragma unroll
            for (int q = 0; q < 4; q++) { accg[i][j][q] = 0.f; accu[i][j][q] = 0.f; }

    #pragma unroll
    for (int s = 0; s < FSTAGES - 1; s++) {
        const int k0 = s * BK;
        const uint32_t so = (uint32_t)(s * FSTG_B);
        cp16(dA0 + so, aP0 + k0 + ac);
        cp16(dA1 + so, aP1 + k0 + ac);
        cp16(dG0 + so, bPg + (size_t)(k0 + bk) * Nb + bc);
        cp16(dG1 + so, bPg + (size_t)(k0 + bk + 16) * Nb + bc);
        cp16(dU0 + so, bPu + (size_t)(k0 + bk) * Nb + bc);
        cp16(dU1 + so, bPu + (size_t)(k0 + bk + 16) * Nb + bc);
        cp_commit();
    }

    const int frow_l = (lane & 7) + ((lane >> 3) & 1) * 8;
    const int fhi_l  = (lane >> 4) & 1;
    const uint32_t aFrag = sbase + (uint32_t)(((wm * 64 + frow_l) * A_PITCH) + fhi_l * 8) * 2u;
    const uint32_t gFrag = sbase + (uint32_t)A_BYTES
                         + (uint32_t)((frow_l * B_PITCH) + wn * 32 + fhi_l * 8) * 2u;

    for (int kt = 0; kt < ktiles; kt++) {
        cp_wait<FSTAGES - 2>();
        __syncthreads();

        const int kn = kt + FSTAGES - 1;
        if (kn < ktiles) {
            const int k0 = kn * BK;
            const uint32_t so = (uint32_t)((kn % FSTAGES) * FSTG_B);
            cp16(dA0 + so, aP0 + k0 + ac);
            cp16(dA1 + so, aP1 + k0 + ac);
            cp16(dG0 + so, bPg + (size_t)(k0 + bk) * Nb + bc);
            cp16(dG1 + so, bPg + (size_t)(k0 + bk + 16) * Nb + bc);
            cp16(dU0 + so, bPu + (size_t)(k0 + bk) * Nb + bc);
            cp16(dU1 + so, bPu + (size_t)(k0 + bk + 16) * Nb + bc);
        }
        cp_commit();

        const uint32_t so = (uint32_t)((kt % FSTAGES) * FSTG_B);
        #pragma unroll
        for (int ks = 0; ks < 2; ks++) {
            const int kk = ks * 16;
            unsigned af[4][4], bg[4][2], bu[4][2];
            #pragma unroll
            for (int i = 0; i < 4; i++)
                ldsm_x4(af[i], aFrag + so + (uint32_t)(i * 16 * A_PITCH + kk) * 2u);
            #pragma unroll
            for (int p = 0; p < 2; p++) {
                unsigned t[4];
                ldsm_x4_t(t, gFrag + so + (uint32_t)(kk * B_PITCH + p * 16) * 2u);
                bg[2 * p][0] = t[0]; bg[2 * p][1] = t[1];
                bg[2 * p + 1][0] = t[2]; bg[2 * p + 1][1] = t[3];
                ldsm_x4_t(t, gFrag + so + (uint32_t)B_BYTES + (uint32_t)(kk * B_PITCH + p * 16) * 2u);
                bu[2 * p][0] = t[0]; bu[2 * p][1] = t[1];
                bu[2 * p + 1][0] = t[2]; bu[2 * p + 1][1] = t[3];
            }
            #pragma unroll
            for (int i = 0; i < 4; i++)
                #pragma unroll
                for (int j = 0; j < 4; j++) {
                    mma_f16(accg[i][j], af[i], bg[j]);
                    mma_f16(accu[i][j], af[i], bu[j]);
                }
        }
    }

    const int g = lane >> 2, tg = lane & 3;
    #pragma unroll
    for (int i = 0; i < 4; i++) {
        #pragma unroll
        for (int half = 0; half < 2; half++) {
            int lr = wm * 64 + i * 16 + g + half * 8;
            int gr = m0 + lr;
            if (MODE == 2 && gr >= Mrows) continue;
            __half* arow;
            float w = 1.f;
            if (MODE == 0) arow = h_act_s + (size_t)gr * Iact;
            else {
                w = g_wt[e * N_TOK + gr];
                arow = h_act_e + ((size_t)e * N_TOK + gr) * Iact;
            }
            #pragma unroll
            for (int j = 0; j < 4; j++) {
                int cc = n0 + wn * 32 + j * 8 + 2 * tg;
                float v0 = w * siluf(accg[i][j][half * 2 + 0]) * accu[i][j][half * 2 + 0];
                float v1 = w * siluf(accg[i][j][half * 2 + 1]) * accu[i][j][half * 2 + 1];
                __half2 hv = __floats2half2_rn(v0, v1);
                *(__half2*)(arow + cc) = hv;
            }
        }
    }
}

// ---------------- down-proj GEMM (k-sliced, optional accumulate) ----------------
#define STAGES 4
#define STG_B (A_BYTES + B_BYTES)   // 18944

template<int MODE>
__global__ void __launch_bounds__(256)
gemm_dn(float* __restrict__ Cg, int Kstride, int N, int kbeg, int klen, int accum) {
    extern __shared__ __half smem[];

    const int tid  = threadIdx.x;
    const int lane = tid & 31, warp = tid >> 5;
    const int wm = warp & 1, wn = warp >> 1;

    const int m0 = blockIdx.y * BM;
    const int n0 = blockIdx.x * BN;
    const int e  = blockIdx.z;

    int Mrows = N_TOK;
    const __half *A, *B;
    if (MODE == 1) { A = h_act_s; B = h_swd; }
    else {
        Mrows = g_cnt[e];
        A = h_act_e + (size_t)e * N_TOK * IMOE;
        B = h_wd + (size_t)e * IMOE * HID;
    }
    if (m0 >= Mrows) return;

    const int ar = tid >> 2, ac = (tid & 3) * 8;
    const __half *aP0, *aP1;
    {
        int r0 = m0 + ar, r1 = r0 + 64;
        if (MODE == 3) { if (r0 >= Mrows) r0 = m0; if (r1 >= Mrows) r1 = m0; }
        aP0 = A + (size_t)r0 * Kstride + kbeg;
        aP1 = A + (size_t)r1 * Kstride + kbeg;
    }
    const int bk = tid >> 4, bc = (tid & 15) * 8;
    const __half* bP = B + (size_t)kbeg * N + n0;

    const uint32_t sbase = (uint32_t)__cvta_generic_to_shared(smem);
    const uint32_t dA0 = sbase + (uint32_t)(ar * A_PITCH + ac) * 2u;
    const uint32_t dA1 = dA0 + 64u * A_PITCH * 2u;
    const uint32_t dB0 = sbase + (uint32_t)A_BYTES + (uint32_t)(bk * B_PITCH + bc) * 2u;
    const uint32_t dB1 = dB0 + 16u * B_PITCH * 2u;

    const int ktiles = klen / BK;

    float acc[4][4][4];
    #pragma unroll
    for (int i = 0; i < 4; i++)
        #pragma unroll
        for (int j = 0; j < 4; j++)
            #pragma unroll
            for (int q = 0; q < 4; q++) acc[i][j][q] = 0.f;

    #pragma unroll
    for (int s = 0; s < STAGES - 1; s++) {
        const int k0 = s * BK;
        const uint32_t so = (uint32_t)(s * STG_B);
        cp16(dA0 + so, aP0 + k0 + ac);
        cp16(dA1 + so, aP1 + k0 + ac);
        cp16(dB0 + so, bP + (size_t)(k0 + bk) * N + bc);
        cp16(dB1 + so, bP + (size_t)(k0 + bk + 16) * N + bc);
        cp_commit();
    }

    const int frow_l = (lane & 7) + ((lane >> 3) & 1) * 8;
    const int fhi_l  = (lane >> 4) & 1;
    const uint32_t aFrag = sbase + (uint32_t)(((wm * 64 + frow_l) * A_PITCH) + fhi_l * 8) * 2u;
    const uint32_t bFrag = sbase + (uint32_t)A_BYTES
                         + (uint32_t)((frow_l * B_PITCH) + wn * 32 + fhi_l * 8) * 2u;

    for (int kt = 0; kt < ktiles; kt++) {
        cp_wait<STAGES - 2>();
        __syncthreads();

        const int kn = kt + STAGES - 1;
        if (kn < ktiles) {
            const int k0 = kn * BK;
            const uint32_t so = (uint32_t)((kn & (STAGES - 1)) * STG_B);
            cp16(dA0 + so, aP0 + k0 + ac);
            cp16(dA1 + so, aP1 + k0 + ac);
            cp16(dB0 + so, bP + (size_t)(k0 + bk) * N + bc);
            cp16(dB1 + so, bP + (size_t)(k0 + bk + 16) * N + bc);
        }
        cp_commit();

        const uint32_t so = (uint32_t)((kt & (STAGES - 1)) * STG_B);
        #pragma unroll
        for (int ks = 0; ks < 2; ks++) {
            const int kk = ks * 16;
            unsigned af[4][4], bf[4][2];
            #pragma unroll
            for (int i = 0; i < 4; i++)
                ldsm_x4(af[i], aFrag + so + (uint32_t)(i * 16 * A_PITCH + kk) * 2u);
            #pragma unroll
            for (int p = 0; p < 2; p++) {
                unsigned t[4];
                ldsm_x4_t(t, bFrag + so + (uint32_t)(kk * B_PITCH + p * 16) * 2u);
                bf[2 * p][0] = t[0]; bf[2 * p][1] = t[1];
                bf[2 * p + 1][0] = t[2]; bf[2 * p + 1][1] = t[3];
            }
            #pragma unroll
            for (int i = 0; i < 4; i++)
                #pragma unroll
                for (int j = 0; j < 4; j++)
                    mma_f16(acc[i][j], af[i], bf[j]);
        }
    }

    const int g = lane >> 2, tg = lane & 3;
    #pragma unroll
    for (int i = 0; i < 4; i++) {
        #pragma unroll
        for (int half = 0; half < 2; half++) {
            int lr = wm * 64 + i * 16 + g + half * 8;
            int gr = m0 + lr;
            if (MODE == 3 && gr >= Mrows) continue;
            float* crow;
            float scale = 1.f;
            if (MODE == 1) { crow = Cg + (size_t)gr * (size_t)N; scale = g_sg[gr]; }
            else {
                int t_ = g_tok [e * N_TOK + gr];
                int s_ = g_slot[e * N_TOK + gr];
                crow = g_part + ((size_t)t_ * 2 + s_) * (size_t)N;
            }
            #pragma unroll
            for (int j = 0; j < 4; j++) {
                int cc = n0 + wn * 32 + j * 8 + 2 * tg;
                float2 v = make_float2(acc[i][j][half * 2 + 0] * scale,
                                       acc[i][j][half * 2 + 1] * scale);
                if (accum) {
                    float2 o = *(float2*)(crow + cc);
                    v.x += o.x; v.y += o.y;
                }
                *(float2*)(crow + cc) = v;
            }
        }
    }
}

// ---------------- combine ----------------
__global__ void combine_kernel(float* __restrict__ out) {
    int idx = blockIdx.x * blockDim.x + threadIdx.x;
    const int total = N_TOK * (HID / 4);
    if (idx >= total) return;
    int n  = idx / (HID / 4);
    int h4 = (idx % (HID / 4)) * 4;
    float4 o  = *(float4*)(out + (size_t)n * HID + h4);
    float4 p0 = *(const float4*)(g_part + ((size_t)n * 2 + 0) * HID + h4);
    float4 p1 = *(const float4*)(g_part + ((size_t)n * 2 + 1) * HID + h4);
    o.x += p0.x + p1.x; o.y += p0.y + p1.y;
    o.z += p0.z + p1.z; o.w += p0.w + p1.w;
    *(float4*)(out + (size_t)n * HID + h4) = o;
}

// ---------------- launch (multi-stream, split-K pipelined shared chain) ----------------
extern "C" void kernel_launch(void* const* d_in, const int* in_sizes, int n_in,
                              void* d_out, int out_size) {
    const float* x    = (const float*)d_in[0];
    const float* gw   = (const float*)d_in[1];
    const float* wgu  = (const float*)d_in[2];
    const float* wd   = (const float*)d_in[3];
    const float* swgu = (const float*)d_in[4];
    const float* swd  = (const float*)d_in[5];
    const float* sgw  = (const float*)d_in[6];
    float* out = (float*)d_out;

    static cudaStream_t s1 = nullptr, s2 = nullptr, s3 = nullptr;
    static cudaEvent_t ev_fork, ev_rt, ev_swgu, ev_swd, ev_wd,
                       ev_g0a, ev_g0b, ev_dn1, ev_exp;
    if (s1 == nullptr) {
        cudaStreamCreateWithFlags(&s1, cudaStreamNonBlocking);
        cudaStreamCreateWithFlags(&s2, cudaStreamNonBlocking);
        cudaStreamCreateWithFlags(&s3, cudaStreamNonBlocking);
        cudaEventCreateWithFlags(&ev_fork, cudaEventDisableTiming);
        cudaEventCreateWithFlags(&ev_rt,   cudaEventDisableTiming);
        cudaEventCreateWithFlags(&ev_swgu, cudaEventDisableTiming);
        cudaEventCreateWithFlags(&ev_swd,  cudaEventDisableTiming);
        cudaEventCreateWithFlags(&ev_wd,   cudaEventDisableTiming);
        cudaEventCreateWithFlags(&ev_g0a,  cudaEventDisableTiming);
        cudaEventCreateWithFlags(&ev_g0b,  cudaEventDisableTiming);
        cudaEventCreateWithFlags(&ev_dn1,  cudaEventDisableTiming);
        cudaEventCreateWithFlags(&ev_exp,  cudaEventDisableTiming);
    }

    const int fsmem = FSTAGES * FSTG_B;   // 82944
    const int dsmem = STAGES * STG_B;     // 75776
    cudaFuncSetAttribute(gemm_gu<0>, cudaFuncAttributeMaxDynamicSharedMemorySize, fsmem);
    cudaFuncSetAttribute(gemm_gu<2>, cudaFuncAttributeMaxDynamicSharedMemorySize, fsmem);
    cudaFuncSetAttribute(gemm_dn<1>, cudaFuncAttributeMaxDynamicSharedMemorySize, dsmem);
    cudaFuncSetAttribute(gemm_dn<3>, cudaFuncAttributeMaxDynamicSharedMemorySize, dsmem);

    const int HALF_N = ISH / 2;   // 2816 (gu0 n-split == dn1 k-split)

    // ---- fork ----
    init_kernel<<<1, 32>>>();
    cudaEventRecord(ev_fork, 0);
    cudaStreamWaitEvent(s1, ev_fork, 0);
    cudaStreamWaitEvent(s2, ev_fork, 0);
    cudaStreamWaitEvent(s3, ev_fork, 0);

    // s1: converts needed by the shared chain + expert down
    {
        int n8 = (HID * 2 * ISH) / 8;
        f2h_kernel<1><<<(n8 + 255) / 256, 256, 0, s1>>>((const float4*)swgu, n8);
        cudaEventRecord(ev_swgu, s1);
        n8 = (ISH * HID) / 8;
        f2h_kernel<2><<<(n8 + 255) / 256, 256, 0, s1>>>((const float4*)swd, n8);
        cudaEventRecord(ev_swd, s1);
        n8 = (NEXP * IMOE * HID) / 8;
        f2h_kernel<4><<<(n8 + 255) / 256, 256, 0, s1>>>((const float4*)wd, n8);
        cudaEventRecord(ev_wd, s1);
    }

    // stream 0: router first (critical path), then shared gate_up halves
    router_kernel<<<N_TOK, 256>>>(x, gw, sgw);
    cudaEventRecord(ev_rt, 0);

    cudaStreamWaitEvent(0, ev_swgu, 0);
    gemm_gu<0><<<dim3(HALF_N / BN, N_TOK / BM, 1), 256, fsmem>>>(HID, 2 * ISH, ISH, 0);
    cudaEventRecord(ev_g0a, 0);
    gemm_gu<0><<<dim3(HALF_N / BN, N_TOK / BM, 1), 256, fsmem>>>(HID, 2 * ISH, ISH, HALF_N);
    cudaEventRecord(ev_g0b, 0);

    // s3: shared down-proj, k-sliced to overlap with gu0b
    cudaStreamWaitEvent(s3, ev_g0a, 0);
    cudaStreamWaitEvent(s3, ev_swd, 0);
    gemm_dn<1><<<dim3(HID / BN, N_TOK / BM, 1), 256, dsmem, s3>>>(out, ISH, HID, 0, HALF_N, 0);
    cudaStreamWaitEvent(s3, ev_g0b, 0);
    gemm_dn<1><<<dim3(HID / BN, N_TOK / BM, 1), 256, dsmem, s3>>>(out, ISH, HID, HALF_N, HALF_N, 1);
    cudaEventRecord(ev_dn1, s3);

    // s2: expert chain (wgu convert feeds it directly)
    {
        int n8 = (NEXP * HID * 2 * IMOE) / 8;
        f2h_kernel<3><<<(n8 + 255) / 256, 256, 0, s2>>>((const float4*)wgu, n8);
    }
    cudaStreamWaitEvent(s2, ev_rt, 0);
    gemm_gu<2><<<dim3(IMOE / BN, N_TOK / BM, NEXP), 256, fsmem, s2>>>(HID, 2 * IMOE, IMOE, 0);
    cudaStreamWaitEvent(s2, ev_wd, 0);
    gemm_dn<3><<<dim3(HID / BN, N_TOK / BM, NEXP), 256, dsmem, s2>>>(nullptr, IMOE, HID, 0, IMOE, 0);
    cudaEventRecord(ev_exp, s2);

    // join: combine on stream 0
    cudaStreamWaitEvent(0, ev_dn1, 0);
    cudaStreamWaitEvent(0, ev_exp, 0);
    {
        int total = N_TOK * (HID / 4);
        combine_kernel<<<(total + 255) / 256, 256>>>(out);
    }
}

// round 10
// speedup vs baseline: 2.4394x; 1.0450x over previous
#include <cuda_runtime.h>
#include <cuda_fp16.h>
#include <cstdint>
#include <math.h>

#define N_TOK 1024
#define HID   2048
#define NEXP  8
#define IMOE  1408
#define ISH   5632
#define QI    (ISH / 4)     // 1408, gu0 n-quarter / dn1 k-chunk

// ---------------- scratch (device globals; no allocation allowed) ----------------
__device__ float g_part [(size_t)N_TOK * 2 * HID];
__device__ float g_sg  [N_TOK];
__device__ float g_wt  [NEXP * N_TOK];
__device__ int   g_cnt [NEXP];
__device__ int   g_tok [NEXP * N_TOK];
__device__ int   g_slot[NEXP * N_TOK];

// fp16 operand mirrors
__device__ __half h_x    [(size_t)N_TOK * HID];
__device__ __half h_swgu [(size_t)HID * (2 * ISH)];
__device__ __half h_swd  [(size_t)ISH * HID];
__device__ __half h_wgu  [(size_t)NEXP * HID * (2 * IMOE)];
__device__ __half h_wd   [(size_t)NEXP * IMOE * HID];
__device__ __half h_act_s[(size_t)N_TOK * ISH];
__device__ __half h_act_e[(size_t)NEXP * N_TOK * IMOE];

// ---------------- helpers ----------------
__device__ __forceinline__ float siluf(float v) { return v / (1.f + expf(-v)); }

__device__ __forceinline__ void mma_f16(float* c, const unsigned* a, const unsigned* b) {
    asm volatile(
        "mma.sync.aligned.m16n8k16.row.col.f32.f16.f16.f32 "
        "{%0,%1,%2,%3}, {%4,%5,%6,%7}, {%8,%9}, {%0,%1,%2,%3};\n"
        : "+f"(c[0]), "+f"(c[1]), "+f"(c[2]), "+f"(c[3])
        : "r"(a[0]), "r"(a[1]), "r"(a[2]), "r"(a[3]), "r"(b[0]), "r"(b[1]));
}
__device__ __forceinline__ void ldsm_x4(unsigned* r, uint32_t a) {
    asm volatile("ldmatrix.sync.aligned.m8n8.x4.shared.b16 {%0,%1,%2,%3}, [%4];"
        : "=r"(r[0]), "=r"(r[1]), "=r"(r[2]), "=r"(r[3]) : "r"(a));
}
__device__ __forceinline__ void ldsm_x4_t(unsigned* r, uint32_t a) {
    asm volatile("ldmatrix.sync.aligned.m8n8.x4.trans.shared.b16 {%0,%1,%2,%3}, [%4];"
        : "=r"(r[0]), "=r"(r[1]), "=r"(r[2]), "=r"(r[3]) : "r"(a));
}
__device__ __forceinline__ void cp16(uint32_t dst, const void* src) {
    asm volatile("cp.async.cg.shared.global [%0], [%1], 16;\n" :: "r"(dst), "l"(src));
}
__device__ __forceinline__ void cp_commit() { asm volatile("cp.async.commit_group;\n"); }
template<int W> __device__ __forceinline__ void cp_wait() {
    asm volatile("cp.async.wait_group %0;\n" :: "n"(W));
}
__device__ __forceinline__ uint4 pack8(float4 v0, float4 v1) {
    __half2 a = __floats2half2_rn(v0.x, v0.y);
    __half2 b = __floats2half2_rn(v0.z, v0.w);
    __half2 c = __floats2half2_rn(v1.x, v1.y);
    __half2 d = __floats2half2_rn(v1.z, v1.w);
    return make_uint4(*(unsigned*)&a, *(unsigned*)&b, *(unsigned*)&c, *(unsigned*)&d);
}

// ---------------- fp32 -> fp16 flat convert ----------------
// W: 2=swd, 3=wgu, 4=wd
template<int W>
__global__ void f2h_kernel(const float4* __restrict__ src, int n8) {
    int i = blockIdx.x * blockDim.x + threadIdx.x;
    if (i >= n8) return;
    __half* dst;
    if      (W == 2) dst = h_swd;
    else if (W == 3) dst = h_wgu;
    else             dst = h_wd;
    uint4 u = pack8(src[2 * i], src[2 * i + 1]);
    *(uint4*)(dst + (size_t)i * 8) = u;
}

// ---------------- swgu column-strip convert: cols [cb, cb+QI) and [ISH+cb, ISH+cb+QI) ----------------
__global__ void f2h_swgu_strip(const float* __restrict__ src, int cb) {
    const int perrow = QI / 8;                 // 176
    const int total = HID * perrow * 2;
    int idx = blockIdx.x * blockDim.x + threadIdx.x;
    if (idx >= total) return;
    int half = idx / (HID * perrow);
    int rem  = idx % (HID * perrow);
    int r = rem / perrow;
    int col = cb + half * ISH + (rem % perrow) * 8;
    const float4* s = (const float4*)(src + (size_t)r * (2 * ISH) + col);
    uint4 u = pack8(s[0], s[1]);
    *(uint4*)(h_swgu + (size_t)r * (2 * ISH) + col) = u;
}

// ---------------- init ----------------
__global__ void init_kernel() {
    if (threadIdx.x < NEXP) g_cnt[threadIdx.x] = 0;
}

// ---------------- router (also emits h_x) ----------------
__global__ void router_kernel(const float* __restrict__ x,
                              const float* __restrict__ gate_w,
                              const float* __restrict__ sgate_w) {
    int n = blockIdx.x;
    int w = threadIdx.x >> 5, lane = threadIdx.x & 31;
    const float* xr = x + (size_t)n * HID;
    __shared__ float s_log[NEXP];
    __shared__ float s_sg;

    float acc = 0.f, accs = 0.f;
    for (int h = lane; h < HID; h += 32) {
        float xv = xr[h];
        acc += xv * gate_w[h * NEXP + w];
        if (w == 0) { accs += xv * sgate_w[h]; h_x[(size_t)n * HID + h] = __float2half(xv); }
    }
    #pragma unroll
    for (int o = 16; o > 0; o >>= 1) {
        acc  += __shfl_down_sync(0xffffffffu, acc, o);
        accs += __shfl_down_sync(0xffffffffu, accs, o);
    }
    if (lane == 0) { s_log[w] = acc; if (w == 0) s_sg = accs; }
    __syncthreads();

    if (threadIdx.x == 0) {
        float mx = s_log[0];
        #pragma unroll
        for (int e = 1; e < NEXP; e++) mx = fmaxf(mx, s_log[e]);
        float p[NEXP], den = 0.f;
        #pragma unroll
        for (int e = 0; e < NEXP; e++) { p[e] = expf(s_log[e] - mx); den += p[e]; }
        float inv = 1.f / den;
        #pragma unroll
        for (int e = 0; e < NEXP; e++) p[e] *= inv;
        int e0 = 0;
        #pragma unroll
        for (int e = 1; e < NEXP; e++) if (p[e] > p[e0]) e0 = e;
        int e1 = (e0 == 0) ? 1 : 0;
        #pragma unroll
        for (int e = 0; e < NEXP; e++) if (e != e0 && p[e] > p[e1]) e1 = e;
        int es[2] = {e0, e1};
        #pragma unroll
        for (int k = 0; k < 2; k++) {
            int e = es[k];
            int pos = atomicAdd(&g_cnt[e], 1);
            g_tok [e * N_TOK + pos] = n;
            g_slot[e * N_TOK + pos] = k;
            g_wt  [e * N_TOK + pos] = p[e];
        }
        g_sg[n] = 1.f / (1.f + expf(-s_sg));
    }
}

// =======================================================================================
#define BM 128
#define BN 128
#define BK 32
#define A_PITCH 40
#define B_PITCH 136
#define A_BYTES (BM * A_PITCH * 2)   // 10240
#define B_BYTES (BK * B_PITCH * 2)   // 8704

// ---------------- FUSED gate_up GEMM + SiLU*up -> fp16 act ----------------
#define FSTAGES 3
#define FSTG_B  (A_BYTES + 2 * B_BYTES)   // 27648

template<int MODE>
__global__ void __launch_bounds__(256)
gemm_gu(int K, int Nb, int Iact, int n_base) {
    extern __shared__ __half smem[];

    const int tid  = threadIdx.x;
    const int lane = tid & 31, warp = tid >> 5;
    const int wm = warp & 1, wn = warp >> 1;

    const int m0 = blockIdx.y * BM;
    const int n0 = n_base + blockIdx.x * BN;
    const int e  = blockIdx.z;

    int Mrows = N_TOK;
    const __half* B;
    if (MODE == 0) B = h_swgu;
    else { Mrows = g_cnt[e]; B = h_wgu + (size_t)e * HID * (2 * IMOE); }
    if (m0 >= Mrows) return;

    const int ar = tid >> 2, ac = (tid & 3) * 8;
    const __half *aP0, *aP1;
    {
        int r0 = m0 + ar, r1 = r0 + 64;
        if (MODE == 2) {
            int i0 = (r0 < Mrows) ? g_tok[e * N_TOK + r0] : 0;
            int i1 = (r1 < Mrows) ? g_tok[e * N_TOK + r1] : 0;
            aP0 = h_x + (size_t)i0 * HID;
            aP1 = h_x + (size_t)i1 * HID;
        } else {
            aP0 = h_x + (size_t)r0 * HID;
            aP1 = h_x + (size_t)r1 * HID;
        }
    }
    const int bk = tid >> 4, bc = (tid & 15) * 8;
    const __half* bPg = B + n0;
    const __half* bPu = B + Iact + n0;

    const uint32_t sbase = (uint32_t)__cvta_generic_to_shared(smem);
    const uint32_t dA0 = sbase + (uint32_t)(ar * A_PITCH + ac) * 2u;
    const uint32_t dA1 = dA0 + 64u * A_PITCH * 2u;
    const uint32_t dG0 = sbase + (uint32_t)A_BYTES + (uint32_t)(bk * B_PITCH + bc) * 2u;
    const uint32_t dG1 = dG0 + 16u * B_PITCH * 2u;
    const uint32_t dU0 = dG0 + (uint32_t)B_BYTES;
    const uint32_t dU1 = dG1 + (uint32_t)B_BYTES;

    const int ktiles = K / BK;

    float accg[4][4][4], accu[4][4][4];
    #pragma unroll
    for (int i = 0; i < 4; i++)
        #pragma unroll
        for (int j = 0; j < 4; j++)
            #pragma unroll
            for (int q = 0; q < 4; q++) { accg[i][j][q] = 0.f; accu[i][j][q] = 0.f; }

    #pragma unroll
    for (int s = 0; s < FSTAGES - 1; s++) {
        const int k0 = s * BK;
        const uint32_t so = (uint32_t)(s * FSTG_B);
        cp16(dA0 + so, aP0 + k0 + ac);
        cp16(dA1 + so, aP1 + k0 + ac);
        cp16(dG0 + so, bPg + (size_t)(k0 + bk) * Nb + bc);
        cp16(dG1 + so, bPg + (size_t)(k0 + bk + 16) * Nb + bc);
        cp16(dU0 + so, bPu + (size_t)(k0 + bk) * Nb + bc);
        cp16(dU1 + so, bPu + (size_t)(k0 + bk + 16) * Nb + bc);
        cp_commit();
    }

    const int frow_l = (lane & 7) + ((lane >> 3) & 1) * 8;
    const int fhi_l  = (lane >> 4) & 1;
    const uint32_t aFrag = sbase + (uint32_t)(((wm * 64 + frow_l) * A_PITCH) + fhi_l * 8) * 2u;
    const uint32_t gFrag = sbase + (uint32_t)A_BYTES
                         + (uint32_t)((frow_l * B_PITCH) + wn * 32 + fhi_l * 8) * 2u;

    for (int kt = 0; kt < ktiles; kt++) {
        cp_wait<FSTAGES - 2>();
        __syncthreads();

        const int kn = kt + FSTAGES - 1;
        if (kn < ktiles) {
            const int k0 = kn * BK;
            const uint32_t so = (uint32_t)((kn % FSTAGES) * FSTG_B);
            cp16(dA0 + so, aP0 + k0 + ac);
            cp16(dA1 + so, aP1 + k0 + ac);
            cp16(dG0 + so, bPg + (size_t)(k0 + bk) * Nb + bc);
            cp16(dG1 + so, bPg + (size_t)(k0 + bk + 16) * Nb + bc);
            cp16(dU0 + so, bPu + (size_t)(k0 + bk) * Nb + bc);
            cp16(dU1 + so, bPu + (size_t)(k0 + bk + 16) * Nb + bc);
        }
        cp_commit();

        const uint32_t so = (uint32_t)((kt % FSTAGES) * FSTG_B);
        #pragma unroll
        for (int ks = 0; ks < 2; ks++) {
            const int kk = ks * 16;
            unsigned af[4][4], bg[4][2], bu[4][2];
            #pragma unroll
            for (int i = 0; i < 4; i++)
                ldsm_x4(af[i], aFrag + so + (uint32_t)(i * 16 * A_PITCH + kk) * 2u);
            #pragma unroll
            for (int p = 0; p < 2; p++) {
                unsigned t[4];
                ldsm_x4_t(t, gFrag + so + (uint32_t)(kk * B_PITCH + p * 16) * 2u);
                bg[2 * p][0] = t[0]; bg[2 * p][1] = t[1];
                bg[2 * p + 1][0] = t[2]; bg[2 * p + 1][1] = t[3];
                ldsm_x4_t(t, gFrag + so + (uint32_t)B_BYTES + (uint32_t)(kk * B_PITCH + p * 16) * 2u);
                bu[2 * p][0] = t[0]; bu[2 * p][1] = t[1];
                bu[2 * p + 1][0] = t[2]; bu[2 * p + 1][1] = t[3];
            }
            #pragma unroll
            for (int i = 0; i < 4; i++)
                #pragma unroll
                for (int j = 0; j < 4; j++) {
                    mma_f16(accg[i][j], af[i], bg[j]);
                    mma_f16(accu[i][j], af[i], bu[j]);
                }
        }
    }

    const int g = lane >> 2, tg = lane & 3;
    #pragma unroll
    for (int i = 0; i < 4; i++) {
        #pragma unroll
        for (int half = 0; half < 2; half++) {
            int lr = wm * 64 + i * 16 + g + half * 8;
            int gr = m0 + lr;
            if (MODE == 2 && gr >= Mrows) continue;
            __half* arow;
            float w = 1.f;
            if (MODE == 0) arow = h_act_s + (size_t)gr * Iact;
            else {
                w = g_wt[e * N_TOK + gr];
                arow = h_act_e + ((size_t)e * N_TOK + gr) * Iact;
            }
            #pragma unroll
            for (int j = 0; j < 4; j++) {
                int cc = n0 + wn * 32 + j * 8 + 2 * tg;
                float v0 = w * siluf(accg[i][j][half * 2 + 0]) * accu[i][j][half * 2 + 0];
                float v1 = w * siluf(accg[i][j][half * 2 + 1]) * accu[i][j][half * 2 + 1];
                __half2 hv = __floats2half2_rn(v0, v1);
                *(__half2*)(arow + cc) = hv;
            }
        }
    }
}

// ---------------- down-proj GEMM (k-sliced, optional accumulate) ----------------
#define STAGES 4
#define STG_B (A_BYTES + B_BYTES)   // 18944

template<int MODE>
__global__ void __launch_bounds__(256)
gemm_dn(float* __restrict__ Cg, int Kstride, int N, int kbeg, int klen, int accum) {
    extern __shared__ __half smem[];

    const int tid  = threadIdx.x;
    const int lane = tid & 31, warp = tid >> 5;
    const int wm = warp & 1, wn = warp >> 1;

    const int m0 = blockIdx.y * BM;
    const int n0 = blockIdx.x * BN;
    const int e  = blockIdx.z;

    int Mrows = N_TOK;
    const __half *A, *B;
    if (MODE == 1) { A = h_act_s; B = h_swd; }
    else {
        Mrows = g_cnt[e];
        A = h_act_e + (size_t)e * N_TOK * IMOE;
        B = h_wd + (size_t)e * IMOE * HID;
    }
    if (m0 >= Mrows) return;

    const int ar = tid >> 2, ac = (tid & 3) * 8;
    const __half *aP0, *aP1;
    {
        int r0 = m0 + ar, r1 = r0 + 64;
        if (MODE == 3) { if (r0 >= Mrows) r0 = m0; if (r1 >= Mrows) r1 = m0; }
        aP0 = A + (size_t)r0 * Kstride + kbeg;
        aP1 = A + (size_t)r1 * Kstride + kbeg;
    }
    const int bk = tid >> 4, bc = (tid & 15) * 8;
    const __half* bP = B + (size_t)kbeg * N + n0;

    const uint32_t sbase = (uint32_t)__cvta_generic_to_shared(smem);
    const uint32_t dA0 = sbase + (uint32_t)(ar * A_PITCH + ac) * 2u;
    const uint32_t dA1 = dA0 + 64u * A_PITCH * 2u;
    const uint32_t dB0 = sbase + (uint32_t)A_BYTES + (uint32_t)(bk * B_PITCH + bc) * 2u;
    const uint32_t dB1 = dB0 + 16u * B_PITCH * 2u;

    const int ktiles = klen / BK;

    float acc[4][4][4];
    #pragma unroll
    for (int i = 0; i < 4; i++)
        #pragma unroll
        for (int j = 0; j < 4; j++)
            #pragma unroll
            for (int q = 0; q < 4; q++) acc[i][j][q] = 0.f;

    #pragma unroll
    for (int s = 0; s < STAGES - 1; s++) {
        const int k0 = s * BK;
        const uint32_t so = (uint32_t)(s * STG_B);
        cp16(dA0 + so, aP0 + k0 + ac);
        cp16(dA1 + so, aP1 + k0 + ac);
        cp16(dB0 + so, bP + (size_t)(k0 + bk) * N + bc);
        cp16(dB1 + so, bP + (size_t)(k0 + bk + 16) * N + bc);
        cp_commit();
    }

    const int frow_l = (lane & 7) + ((lane >> 3) & 1) * 8;
    const int fhi_l  = (lane >> 4) & 1;
    const uint32_t aFrag = sbase + (uint32_t)(((wm * 64 + frow_l) * A_PITCH) + fhi_l * 8) * 2u;
    const uint32_t bFrag = sbase + (uint32_t)A_BYTES
                         + (uint32_t)((frow_l * B_PITCH) + wn * 32 + fhi_l * 8) * 2u;

    for (int kt = 0; kt < ktiles; kt++) {
        cp_wait<STAGES - 2>();
        __syncthreads();

        const int kn = kt + STAGES - 1;
        if (kn < ktiles) {
            const int k0 = kn * BK;
            const uint32_t so = (uint32_t)((kn & (STAGES - 1)) * STG_B);
            cp16(dA0 + so, aP0 + k0 + ac);
            cp16(dA1 + so, aP1 + k0 + ac);
            cp16(dB0 + so, bP + (size_t)(k0 + bk) * N + bc);
            cp16(dB1 + so, bP + (size_t)(k0 + bk + 16) * N + bc);
        }
        cp_commit();

        const uint32_t so = (uint32_t)((kt & (STAGES - 1)) * STG_B);
        #pragma unroll
        for (int ks = 0; ks < 2; ks++) {
            const int kk = ks * 16;
            unsigned af[4][4], bf[4][2];
            #pragma unroll
            for (int i = 0; i < 4; i++)
                ldsm_x4(af[i], aFrag + so + (uint32_t)(i * 16 * A_PITCH + kk) * 2u);
            #pragma unroll
            for (int p = 0; p < 2; p++) {
                unsigned t[4];
                ldsm_x4_t(t, bFrag + so + (uint32_t)(kk * B_PITCH + p * 16) * 2u);
                bf[2 * p][0] = t[0]; bf[2 * p][1] = t[1];
                bf[2 * p + 1][0] = t[2]; bf[2 * p + 1][1] = t[3];
            }
            #pragma unroll
            for (int i = 0; i < 4; i++)
                #pragma unroll
                for (int j = 0; j < 4; j++)
                    mma_f16(acc[i][j], af[i], bf[j]);
        }
    }

    const int g = lane >> 2, tg = lane & 3;
    #pragma unroll
    for (int i = 0; i < 4; i++) {
        #pragma unroll
        for (int half = 0; half < 2; half++) {
            int lr = wm * 64 + i * 16 + g + half * 8;
            int gr = m0 + lr;
            if (MODE == 3 && gr >= Mrows) continue;
            float* crow;
            float scale = 1.f;
            if (MODE == 1) { crow = Cg + (size_t)gr * (size_t)N; scale = g_sg[gr]; }
            else {
                int t_ = g_tok [e * N_TOK + gr];
                int s_ = g_slot[e * N_TOK + gr];
                crow = g_part + ((size_t)t_ * 2 + s_) * (size_t)N;
            }
            #pragma unroll
            for (int j = 0; j < 4; j++) {
                int cc = n0 + wn * 32 + j * 8 + 2 * tg;
                float2 v = make_float2(acc[i][j][half * 2 + 0] * scale,
                                       acc[i][j][half * 2 + 1] * scale);
                if (accum) {
                    float2 o = *(float2*)(crow + cc);
                    v.x += o.x; v.y += o.y;
                }
                *(float2*)(crow + cc) = v;
            }
        }
    }
}

// ---------------- combine ----------------
__global__ void combine_kernel(float* __restrict__ out) {
    int idx = blockIdx.x * blockDim.x + threadIdx.x;
    const int total = N_TOK * (HID / 4);
    if (idx >= total) return;
    int n  = idx / (HID / 4);
    int h4 = (idx % (HID / 4)) * 4;
    float4 o  = *(float4*)(out + (size_t)n * HID + h4);
    float4 p0 = *(const float4*)(g_part + ((size_t)n * 2 + 0) * HID + h4);
    float4 p1 = *(const float4*)(g_part + ((size_t)n * 2 + 1) * HID + h4);
    o.x += p0.x + p1.x; o.y += p0.y + p1.y;
    o.z += p0.z + p1.z; o.w += p0.w + p1.w;
    *(float4*)(out + (size_t)n * HID + h4) = o;
}

// ---------------- launch: 3 side streams (round-8 budget), round-9 slicing ----------------
extern "C" void kernel_launch(void* const* d_in, const int* in_sizes, int n_in,
                              void* d_out, int out_size) {
    const float* x    = (const float*)d_in[0];
    const float* gw   = (const float*)d_in[1];
    const float* wgu  = (const float*)d_in[2];
    const float* wd   = (const float*)d_in[3];
    const float* swgu = (const float*)d_in[4];
    const float* swd  = (const float*)d_in[5];
    const float* sgw  = (const float*)d_in[6];
    float* out = (float*)d_out;

    static cudaStream_t s1 = nullptr, s2 = nullptr, s3 = nullptr;
    static cudaEvent_t ev_fork, ev_rt, ev_st[4], ev_swd, ev_wd,
                       ev_g0[4], ev_dn1, ev_exp;
    if (s1 == nullptr) {
        cudaStreamCreateWithFlags(&s1, cudaStreamNonBlocking);
        cudaStreamCreateWithFlags(&s2, cudaStreamNonBlocking);
        cudaStreamCreateWithFlags(&s3, cudaStreamNonBlocking);
        cudaEventCreateWithFlags(&ev_fork, cudaEventDisableTiming);
        cudaEventCreateWithFlags(&ev_rt,   cudaEventDisableTiming);
        for (int q = 0; q < 4; q++) {
            cudaEventCreateWithFlags(&ev_st[q], cudaEventDisableTiming);
            cudaEventCreateWithFlags(&ev_g0[q], cudaEventDisableTiming);
        }
        cudaEventCreateWithFlags(&ev_swd,  cudaEventDisableTiming);
        cudaEventCreateWithFlags(&ev_wd,   cudaEventDisableTiming);
        cudaEventCreateWithFlags(&ev_dn1,  cudaEventDisableTiming);
        cudaEventCreateWithFlags(&ev_exp,  cudaEventDisableTiming);
    }

    const int fsmem = FSTAGES * FSTG_B;   // 82944
    const int dsmem = STAGES * STG_B;     // 75776
    cudaFuncSetAttribute(gemm_gu<0>, cudaFuncAttributeMaxDynamicSharedMemorySize, fsmem);
    cudaFuncSetAttribute(gemm_gu<2>, cudaFuncAttributeMaxDynamicSharedMemorySize, fsmem);
    cudaFuncSetAttribute(gemm_dn<1>, cudaFuncAttributeMaxDynamicSharedMemorySize, dsmem);
    cudaFuncSetAttribute(gemm_dn<3>, cudaFuncAttributeMaxDynamicSharedMemorySize, dsmem);

    // ---- fork ----
    init_kernel<<<1, 32>>>();
    cudaEventRecord(ev_fork, 0);
    cudaStreamWaitEvent(s1, ev_fork, 0);
    cudaStreamWaitEvent(s2, ev_fork, 0);
    cudaStreamWaitEvent(s3, ev_fork, 0);

    // s1: swgu strips first (unblock gu0 quarters asap), then swd, wd
    {
        const int sg = (HID * (QI / 8) * 2 + 255) / 256;
        for (int q = 0; q < 4; q++) {
            f2h_swgu_strip<<<sg, 256, 0, s1>>>(swgu, q * QI);
            cudaEventRecord(ev_st[q], s1);
        }
        int n8 = (ISH * HID) / 8;
        f2h_kernel<2><<<(n8 + 255) / 256, 256, 0, s1>>>((const float4*)swd, n8);
        cudaEventRecord(ev_swd, s1);
        n8 = (NEXP * IMOE * HID) / 8;
        f2h_kernel<4><<<(n8 + 255) / 256, 256, 0, s1>>>((const float4*)wd, n8);
        cudaEventRecord(ev_wd, s1);
    }

    // stream 0: router, then gu0 n-quarters gated on strip converts
    router_kernel<<<N_TOK, 256>>>(x, gw, sgw);
    cudaEventRecord(ev_rt, 0);
    for (int q = 0; q < 4; q++) {
        cudaStreamWaitEvent(0, ev_st[q], 0);
        gemm_gu<0><<<dim3(QI / BN, N_TOK / BM, 1), 256, fsmem>>>(HID, 2 * ISH, ISH, q * QI);
        cudaEventRecord(ev_g0[q], 0);
    }

    // s3: dn1 k-chunks, chained quarter-by-quarter against gu0
    cudaStreamWaitEvent(s3, ev_swd, 0);
    for (int q = 0; q < 4; q++) {
        cudaStreamWaitEvent(s3, ev_g0[q], 0);
        gemm_dn<1><<<dim3(HID / BN, N_TOK / BM, 1), 256, dsmem, s3>>>(
            out, ISH, HID, q * QI, QI, q > 0 ? 1 : 0);
    }
    cudaEventRecord(ev_dn1, s3);

    // s2: wgu convert, then expert chain
    {
        int n8 = (NEXP * HID * 2 * IMOE) / 8;
        f2h_kernel<3><<<(n8 + 255) / 256, 256, 0, s2>>>((const float4*)wgu, n8);
    }
    cudaStreamWaitEvent(s2, ev_rt, 0);
    gemm_gu<2><<<dim3(IMOE / BN, N_TOK / BM, NEXP), 256, fsmem, s2>>>(HID, 2 * IMOE, IMOE, 0);
    cudaStreamWaitEvent(s2, ev_wd, 0);
    gemm_dn<3><<<dim3(HID / BN, N_TOK / BM, NEXP), 256, dsmem, s2>>>(nullptr, IMOE, HID, 0, IMOE, 0);
    cudaEventRecord(ev_exp, s2);

    // join: combine on stream 0
    cudaStreamWaitEvent(0, ev_dn1, 0);
    cudaStreamWaitEvent(0, ev_exp, 0);
    {
        int total = N_TOK * (HID / 4);
        combine_kernel<<<(total + 255) / 256, 256>>>(out);
    }
}